// round 11
// baseline (speedup 1.0000x reference)
#include <cuda_runtime.h>
#include <cuda_fp16.h>
#include <mma.h>
#include <math.h>
#include <stdint.h>

using namespace nvcuda;

#define N_CELLS 16384
#define D_IN    512
#define D_HID   1024
#define D_OUT   512
#define G3H     3072
#define NF      8
#define FS      2048

// ---------------- device scratch (static, allocation-free) ----------------
__device__ float  d_xvec[256];                         // fused bias for MLP1
__device__ __half d_w1t[256 * 1024];                   // [N=256][K=1024]
__device__ __half d_w2t[512 * 256];                    // [N=512][K=256] ([Wa2;-Wg2]^T)
__device__ float  d_bias2[512];                        // ba2 - bg2
__device__ __half d_whh_t[(size_t)G3H * D_HID];        // W_hh^T [3072][1024]
__device__ __half d_wih_t[(size_t)G3H * D_OUT];        // W_ih[:512]^T [3072][512]
__device__ __half d_hid_h[(size_t)N_CELLS * D_HID];    // fp16 hiddens
__device__ __half d_srelu_h[(size_t)N_CELLS * 256];    // fp16 relu acts (a|g)
__device__ __half d_soutput_h[(size_t)N_CELLS * 512];  // fp16 output = a - g
__device__ float  d_tension[N_CELLS];
__device__ float  d_ebuf[N_CELLS];
__device__ __half d_gi_h[(size_t)N_CELLS * G3H];       // fp16 gi preacts
__device__ __half d_gh_h[(size_t)N_CELLS * G3H];       // fp16 gh preacts
__device__ float  d_hpost[(size_t)N_CELLS * D_HID];
__device__ float  d_sumall[NF * D_HID];
__device__ float  d_sumpos[NF * D_HID];
__device__ float  d_sumneg[NF * D_HID];
__device__ float  d_meanp[D_HID];
__device__ float  d_meann[D_HID];
__device__ float  d_F[NF * D_HID];
__device__ float  d_gop[D_HID];
__device__ int    d_cntp[NF];
__device__ int    d_cntn[NF];
__device__ int    d_cnt_tot[2];
__device__ float  d_tsum;
__device__ float  d_sumexp;
__device__ int    d_tmax_i;
__device__ float  d_cout[512];

// ---------------- cp.async helpers ----------------
__device__ __forceinline__ void cp16(uint32_t daddr, const void* src) {
    asm volatile("cp.async.cg.shared.global [%0], [%1], 16;" :: "r"(daddr), "l"(src));
}
__device__ __forceinline__ void cp_commit() {
    asm volatile("cp.async.commit_group;" ::: "memory");
}
template <int N>
__device__ __forceinline__ void cp_wait() {
    asm volatile("cp.async.wait_group %0;" :: "n"(N) : "memory");
}

__device__ __forceinline__ float fast_sigmoid(float x) {
    return 1.0f / (1.0f + __expf(-x));
}
__device__ __forceinline__ float fast_tanh(float x) {
    float a = fabsf(x);
    float e = __expf(-2.0f * a);
    float r = (1.0f - e) / (1.0f + e);
    return copysignf(r, x);
}

// ---------------- pipelined fp16 WMMA GEMM (proven config) ----------------
// C[M x Ntot] = A[M x K] (fp16, row-major) * Bt[Ntot x K] (fp16, K-major)^T
// Block tile 128x128, BK=32, 3-stage cp.async pipeline, 256 threads,
// warp grid 2x4 (warp tile 64x32), fp32 accumulate, 2 CTAs/SM.
// modes: 1 = relu, 2 = + rowv[m]*colv[n], 8 = write half to Ch, 16 = skip fp32 C
#define STAGE_H 10240   // halves per stage: A 128x40 + B 128x40

__global__ void __launch_bounds__(256, 2) gemm_fp16(
    const __half* __restrict__ A, int lda,
    const __half* __restrict__ Bt,
    float* __restrict__ C, __half* __restrict__ Ch, int ldc,
    int K, int mode,
    const float* __restrict__ bias,
    const float* __restrict__ rowv,
    const float* __restrict__ colv)
{
    extern __shared__ __align__(16) char smem_raw[];
    __half* smem = (__half*)smem_raw;
    const uint32_t sbase = (uint32_t)__cvta_generic_to_shared(smem);

    const int tid  = threadIdx.x;
    const int bm   = blockIdx.y * 128;
    const int bn   = blockIdx.x * 128;
    const int warp = tid >> 5;
    const int wr   = warp & 1;   // 2 warp rows of 64
    const int wc   = warp >> 1;  // 4 warp cols of 32

    wmma::fragment<wmma::accumulator, 16, 16, 16, float> acc[4][2];
#pragma unroll
    for (int i = 0; i < 4; i++)
#pragma unroll
        for (int j = 0; j < 2; j++) wmma::fill_fragment(acc[i][j], 0.0f);

    const int crow = tid >> 1;           // 0..127
    const int ccol = (tid & 1) << 4;     // 0 or 16 (halves)

#define ISSUE(KT)                                                              \
    {                                                                          \
        uint32_t so = ((KT) % 3) * STAGE_H;                                    \
        int k0 = (KT) << 5;                                                    \
        _Pragma("unroll")                                                      \
        for (int h2 = 0; h2 < 2; h2++) {                                       \
            int cc = ccol + h2 * 8;                                            \
            cp16(sbase + (so + crow * 40 + cc) * 2,                            \
                 A + (size_t)(bm + crow) * lda + k0 + cc);                     \
            cp16(sbase + (so + 5120 + crow * 40 + cc) * 2,                     \
                 Bt + (size_t)(bn + crow) * K + k0 + cc);                      \
        }                                                                      \
        cp_commit();                                                           \
    }

#define MMA_TILE(KT)                                                           \
    {                                                                          \
        __half* As = smem + ((KT) % 3) * STAGE_H;                              \
        __half* Bs = As + 5120;                                                \
        _Pragma("unroll")                                                      \
        for (int kk = 0; kk < 32; kk += 16) {                                  \
            wmma::fragment<wmma::matrix_a, 16, 16, 16, __half, wmma::row_major> af[4]; \
            wmma::fragment<wmma::matrix_b, 16, 16, 16, __half, wmma::col_major> bf[2]; \
            _Pragma("unroll")                                                  \
            for (int i = 0; i < 4; i++)                                        \
                wmma::load_matrix_sync(af[i], As + (wr * 64 + i * 16) * 40 + kk, 40); \
            _Pragma("unroll")                                                  \
            for (int j = 0; j < 2; j++)                                        \
                wmma::load_matrix_sync(bf[j], Bs + (wc * 32 + j * 16) * 40 + kk, 40); \
            _Pragma("unroll")                                                  \
            for (int i = 0; i < 4; i++)                                        \
                _Pragma("unroll")                                              \
                for (int j = 0; j < 2; j++)                                    \
                    wmma::mma_sync(acc[i][j], af[i], bf[j], acc[i][j]);        \
        }                                                                      \
    }

    const int nk = K >> 5;
    ISSUE(0)
    ISSUE(1)

    for (int kt = 0; kt < nk - 1; kt++) {
        cp_wait<1>();
        __syncthreads();
        if (kt + 2 < nk) ISSUE(kt + 2)
        MMA_TILE(kt)
    }
    cp_wait<0>();
    __syncthreads();
    MMA_TILE(nk - 1)
#undef ISSUE
#undef MMA_TILE

    // epilogue in two 64-col halves staged through shared (floats, stride 72)
    float* Cs = (float*)smem;
#pragma unroll
    for (int h = 0; h < 2; h++) {
        __syncthreads();
        if ((wc >> 1) == h) {
            const int lc = (wc & 1) << 5;
#pragma unroll
            for (int i = 0; i < 4; i++)
#pragma unroll
                for (int j = 0; j < 2; j++)
                    wmma::store_matrix_sync(Cs + (wr * 64 + i * 16) * 72 + lc + j * 16,
                                            acc[i][j], 72, wmma::mem_row_major);
        }
        __syncthreads();
#pragma unroll
        for (int it = 0; it < 32; it++) {
            int idx = it * 256 + tid;
            int r = idx >> 6, c = idx & 63;
            int gr = bm + r, gc = bn + (h << 6) + c;
            float v = Cs[r * 72 + c] + bias[gc];
            if (mode & 2) v += rowv[gr] * colv[gc];
            if (mode & 1) v = fmaxf(v, 0.0f);
            if (!(mode & 16)) C[(size_t)gr * ldc + gc] = v;
            if (mode & 8)  Ch[(size_t)gr * ldc + gc] = __float2half(v);
        }
    }
}

// ---------------- prep kernels ----------------
__global__ void cvt_half(const float* __restrict__ src, __half* __restrict__ dst) {
    size_t i = (size_t)blockIdx.x * 256 + threadIdx.x;
    float4 v = reinterpret_cast<const float4*>(src)[i];
    __half2* d = reinterpret_cast<__half2*>(dst) + i * 2;
    d[0] = __floats2half2_rn(v.x, v.y);
    d[1] = __floats2half2_rn(v.z, v.w);
}

// dst[c][r] = (half)src[r][c]; src R x Ccols, dst stride R
__global__ void transpose_half(const float* __restrict__ src, __half* __restrict__ dst,
                               int R, int Ccols) {
    __shared__ float tile[32][33];
    int c0 = blockIdx.x * 32, r0 = blockIdx.y * 32;
    int x = threadIdx.x, y = threadIdx.y;   // (32, 8)
#pragma unroll
    for (int i = 0; i < 32; i += 8)
        tile[y + i][x] = src[(size_t)(r0 + y + i) * Ccols + c0 + x];
    __syncthreads();
#pragma unroll
    for (int i = 0; i < 32; i += 8)
        dst[(size_t)(c0 + y + i) * R + r0 + x] = __float2half(tile[x][y + i]);
}

__global__ void w1t_kernel(const float* __restrict__ Wa1, const float* __restrict__ Wg1) {
    int n = blockIdx.y;                         // 0..255
    int k = blockIdx.x * 256 + threadIdx.x;     // 0..1023
    float v = (n < 128) ? Wa1[(size_t)(512 + k) * 128 + n]
                        : Wg1[(size_t)(512 + k) * 128 + (n - 128)];
    d_w1t[n * 1024 + k] = __float2half(v);
}

__global__ void w2t_kernel(const float* __restrict__ Wa2, const float* __restrict__ ba2,
                           const float* __restrict__ Wg2, const float* __restrict__ bg2) {
    int n = blockIdx.y;                // 0..511
    int k = threadIdx.x;               // 0..255
    float v = (k < 128) ? Wa2[(size_t)k * 512 + n] : -Wg2[(size_t)(k - 128) * 512 + n];
    d_w2t[n * 256 + k] = __float2half(v);
    if (k == 0) d_bias2[n] = ba2[n] - bg2[n];
}

// init: zero accumulators, seed out[0..511] with bo
__global__ void init_kernel(const float* __restrict__ bo, float* __restrict__ out) {
    int gid = blockIdx.x * 512 + threadIdx.x;   // grid 64 x 512
    if (gid < NF * D_HID) {
        d_sumall[gid] = 0.0f; d_sumpos[gid] = 0.0f; d_sumneg[gid] = 0.0f;
    }
    if (gid < 512) { d_cout[gid] = 0.0f; out[gid] = bo[gid]; }
    if (gid < NF + 512 && gid >= 512) { d_cntp[gid - 512] = 0; d_cntn[gid - 512] = 0; }
    if (gid == 0) { d_tsum = 0.0f; d_sumexp = 0.0f; d_tmax_i = 0; }
}

__global__ void count_kernel(const int* __restrict__ pos) {
    int i = blockIdx.x * 256 + threadIdx.x;
    int p = pos[i];
    int f = i >> 11;
    if (p > 0) atomicAdd(&d_cntp[f], 1);
    else if (p < 0) atomicAdd(&d_cntn[f], 1);
}

// warp-per-column GEMV: xvec[n] = bias[n] + sum_k x[k]*W1[k][n]
__global__ void prep_kernel(const float* __restrict__ x,
                            const float* __restrict__ Wa1, const float* __restrict__ ba1,
                            const float* __restrict__ Wg1, const float* __restrict__ bg1) {
    int n = (blockIdx.x << 4) + (threadIdx.x >> 5);  // grid 16 x 512 -> n 0..255
    int lane = threadIdx.x & 31;
    const float* W = (n < 128) ? Wa1 : Wg1;
    int col = n & 127;
    float s = 0.0f;
    for (int k = lane; k < D_IN; k += 32) s += x[k] * W[k * 128 + col];
#pragma unroll
    for (int off = 16; off; off >>= 1) s += __shfl_xor_sync(0xffffffffu, s, off);
    if (lane == 0) d_xvec[n] = s + ((n < 128) ? ba1[col] : bg1[col]);
}

// ---------------- elementwise / reduction kernels ----------------
__global__ void tension_kernel() {
    int row  = blockIdx.x * 8 + (threadIdx.x >> 5);
    int lane = threadIdx.x & 31;
    const __half2* o = reinterpret_cast<const __half2*>(d_soutput_h + (size_t)row * 512);
    float s = 0.0f;
    for (int c = lane; c < 256; c += 32) {
        float2 v = __half22float2(o[c]);
        s += v.x * v.x + v.y * v.y;
    }
#pragma unroll
    for (int off = 16; off; off >>= 1) s += __shfl_xor_sync(0xffffffffu, s, off);
    __shared__ float wsum[8];
    __shared__ float wmax[8];
    float t = s * (1.0f / 512.0f);
    if (lane == 0) {
        d_tension[row] = t;
        wsum[threadIdx.x >> 5] = t;
        wmax[threadIdx.x >> 5] = t;
    }
    __syncthreads();
    if (threadIdx.x == 0) {
        float a = 0.0f, m = 0.0f;
        for (int w = 0; w < 8; w++) { a += wsum[w]; m = fmaxf(m, wmax[w]); }
        atomicAdd(&d_tsum, a);
        atomicMax(&d_tmax_i, __float_as_int(m));   // tension >= 0, int cmp ok
    }
}

__global__ void sumexp_kernel() {
    int i = blockIdx.x * 256 + threadIdx.x;
    float tmax = __int_as_float(d_tmax_i);
    float e = __expf(d_tension[i] - tmax);
    d_ebuf[i] = e;
    __shared__ float sh[256];
    sh[threadIdx.x] = e;
    __syncthreads();
    for (int s = 128; s; s >>= 1) {
        if (threadIdx.x < s) sh[threadIdx.x] += sh[threadIdx.x + s];
        __syncthreads();
    }
    if (threadIdx.x == 0) atomicAdd(&d_sumexp, sh[0]);
}

// GRU combine + wealth mod + clip; half2 vectorized (2 elems/thread)
__global__ void gru_kernel(const float* __restrict__ hid, const float* __restrict__ wealth) {
    size_t t = (size_t)blockIdx.x * 256 + threadIdx.x;   // 0 .. 8.39M
    int i  = (int)(t >> 9);          // row
    int j2 = (int)(t & 511);         // half2 index within 1024-wide row
    const __half2* gi = reinterpret_cast<const __half2*>(d_gi_h + (size_t)i * G3H);
    const __half2* gh = reinterpret_cast<const __half2*>(d_gh_h + (size_t)i * G3H);
    float2 gir = __half22float2(gi[j2]);
    float2 giz = __half22float2(gi[j2 + 512]);
    float2 gin = __half22float2(gi[j2 + 1024]);
    float2 ghr = __half22float2(gh[j2]);
    float2 ghz = __half22float2(gh[j2 + 512]);
    float2 ghn = __half22float2(gh[j2 + 1024]);
    float2 h = *reinterpret_cast<const float2*>(hid + (size_t)i * 1024 + j2 * 2);
    float w = wealth[i];
    float mod = 0.9f + 0.1f * fminf(fmaxf(w, 0.1f), 2.0f);

    float r0 = fast_sigmoid(gir.x + ghr.x);
    float z0 = fast_sigmoid(giz.x + ghz.x);
    float n0 = fast_tanh(gin.x + r0 * ghn.x);
    float nh0 = fminf(fmaxf(((1.0f - z0) * n0 + z0 * h.x) * mod, -10.0f), 10.0f);

    float r1 = fast_sigmoid(gir.y + ghr.y);
    float z1 = fast_sigmoid(giz.y + ghz.y);
    float n1 = fast_tanh(gin.y + r1 * ghn.y);
    float nh1 = fminf(fmaxf(((1.0f - z1) * n1 + z1 * h.y) * mod, -10.0f), 10.0f);

    *reinterpret_cast<float2*>(d_hpost + (size_t)i * 1024 + j2 * 2) = make_float2(nh0, nh1);
}

// per-faction column sums, row-chunked for parallelism: grid (8, 8, 8)
__global__ void stats_kernel(const int* __restrict__ pos) {
    int f = blockIdx.x;                          // faction
    int j = blockIdx.y * 128 + threadIdx.x;      // column
    int r0 = blockIdx.z * 256;                   // row chunk within faction
    int base = f * FS + r0;
    float sa = 0.0f, sp = 0.0f, sn = 0.0f;
    for (int r = 0; r < 256; r++) {
        float v = d_hpost[(size_t)(base + r) * D_HID + j];
        int p = pos[base + r];
        sa += v;
        if (p > 0) sp += v; else if (p < 0) sn += v;
    }
    atomicAdd(&d_sumall[f * D_HID + j], sa);
    atomicAdd(&d_sumpos[f * D_HID + j], sp);
    atomicAdd(&d_sumneg[f * D_HID + j], sn);
}

__global__ void statsfinal_kernel() {
    int j = threadIdx.x;           // 0..1023
    int cp = 0, cn = 0;
    for (int f = 0; f < NF; f++) { cp += d_cntp[f]; cn += d_cntn[f]; }
    float sp = 0.0f, sn = 0.0f;
    for (int f = 0; f < NF; f++) { sp += d_sumpos[f * D_HID + j]; sn += d_sumneg[f * D_HID + j]; }
    float mp = sp / (float)max(cp, 1);
    float mn = sn / (float)max(cn, 1);
    d_meanp[j] = mp; d_meann[j] = mn;
    float g = 0.0f;
    for (int f = 0; f < NF; f++) {
        float adj = d_sumall[f * D_HID + j];
        if (cp >= 2) adj += 0.1f * ((float)d_cntp[f] * mp - d_sumpos[f * D_HID + j]);
        if (cn >= 2) adj += 0.1f * ((float)d_cntn[f] * mn - d_sumneg[f * D_HID + j]);
        float F = adj * (1.0f / (float)FS);
        d_F[f * D_HID + j] = F;
        g += F;
    }
    d_gop[j] = g * (1.0f / (float)NF);
    if (j == 0) { d_cnt_tot[0] = cp; d_cnt_tot[1] = cn; }
}

// apply syncs + debate; float4 per thread
__global__ void final_kernel(const int* __restrict__ pos, const int* __restrict__ step,
                             float* __restrict__ out) {
    size_t t = (size_t)blockIdx.x * 256 + threadIdx.x;   // 0 .. 4.19M
    int i = (int)(t >> 8);
    int j = (int)(t & 255) * 4;
    float4 h4 = *reinterpret_cast<const float4*>(d_hpost + (size_t)i * 1024 + j);
    int p = pos[i];
    int cp = d_cnt_tot[0], cn = d_cnt_tot[1];
    float* hv = (float*)&h4;
    if (p > 0 && cp >= 2) {
        const float4 m4 = *reinterpret_cast<const float4*>(d_meanp + j);
        const float* mv = (const float*)&m4;
#pragma unroll
        for (int q = 0; q < 4; q++) hv[q] = 0.9f * hv[q] + 0.1f * mv[q];
    } else if (p < 0 && cn >= 2) {
        const float4 m4 = *reinterpret_cast<const float4*>(d_meann + j);
        const float* mv = (const float*)&m4;
#pragma unroll
        for (int q = 0; q < 4; q++) hv[q] = 0.9f * hv[q] + 0.1f * mv[q];
    }
    int f = i >> 11;
    const float4 F4 = *reinterpret_cast<const float4*>(d_F + f * D_HID + j);
    const float* Fv = (const float*)&F4;
#pragma unroll
    for (int q = 0; q < 4; q++) hv[q] = 0.85f * hv[q] + 0.15f * Fv[q];
    if (*step > 5 && (i & (FS - 1)) < (FS / 4)) {
        const float4 g4 = *reinterpret_cast<const float4*>(d_gop + j);
        const float* gv = (const float*)&g4;
#pragma unroll
        for (int q = 0; q < 4; q++) hv[q] = 0.85f * hv[q] + 0.15f * gv[q];
    }
    float* o = out + 513 + (size_t)i * 1024 + j;
#pragma unroll
    for (int q = 0; q < 4; q++) o[q] = hv[q];
}

// combined_out = sum_i softmax(tension)_i * output[i,:]; 256 blocks x 64 rows
__global__ void wsum_kernel() {
    int r0 = blockIdx.x * 64;
    float inv = 1.0f / d_sumexp;
    int t = threadIdx.x;
    float c0 = 0.0f, c1 = 0.0f;
    for (int r = r0; r < r0 + 64; r++) {
        float w = d_ebuf[r] * inv;
        const __half* o = d_soutput_h + (size_t)r * 512;
        c0 += w * __half2float(o[t]);
        c1 += w * __half2float(o[t + 256]);
    }
    atomicAdd(&d_cout[t], c0);
    atomicAdd(&d_cout[t + 256], c1);
}

// split-K GEMV: out[t] += sum_{k in chunk} cout[k]*Wo[k][t]; bias seeded in init
__global__ void pred_kernel(const float* __restrict__ Wo, float* __restrict__ out) {
    __shared__ float co[64];
    int b = blockIdx.x;      // 0..7
    int t = threadIdx.x;     // 0..511
    if (t < 64) co[t] = d_cout[b * 64 + t];
    __syncthreads();
    float s = 0.0f;
#pragma unroll 8
    for (int k = 0; k < 64; k++) s += co[k] * Wo[(size_t)(b * 64 + k) * 512 + t];
    atomicAdd(&out[t], s);
    if (b == 0 && t == 0) out[512] = d_tsum * (1.0f / (float)N_CELLS);
}

// ---------------- launch ----------------
extern "C" void kernel_launch(void* const* d_in, const int* in_sizes, int n_in,
                              void* d_out, int out_size) {
    const float* x        = (const float*)d_in[0];
    const float* hiddens  = (const float*)d_in[1];
    const float* wealth   = (const float*)d_in[2];
    const float* Wa1      = (const float*)d_in[3];
    const float* ba1      = (const float*)d_in[4];
    const float* Wa2      = (const float*)d_in[5];
    const float* ba2      = (const float*)d_in[6];
    const float* Wg1      = (const float*)d_in[7];
    const float* bg1      = (const float*)d_in[8];
    const float* Wg2      = (const float*)d_in[9];
    const float* bg2      = (const float*)d_in[10];
    const float* W_ih     = (const float*)d_in[11];
    const float* W_hh     = (const float*)d_in[12];
    const float* b_ih     = (const float*)d_in[13];
    const float* b_hh     = (const float*)d_in[14];
    const float* Wo       = (const float*)d_in[15];
    const float* bo       = (const float*)d_in[16];
    const int*   positions= (const int*)d_in[17];
    const int*   step     = (const int*)d_in[18];
    float* out = (float*)d_out;

    void *p_srelu_h, *p_soutput_h, *p_w1t, *p_w2t, *p_bias2, *p_xvec;
    void *p_hid_h, *p_whh_t, *p_wih_t, *p_gi_h, *p_gh_h, *p_tension;
    cudaGetSymbolAddress(&p_srelu_h,   d_srelu_h);
    cudaGetSymbolAddress(&p_soutput_h, d_soutput_h);
    cudaGetSymbolAddress(&p_w1t,       d_w1t);
    cudaGetSymbolAddress(&p_w2t,       d_w2t);
    cudaGetSymbolAddress(&p_bias2,     d_bias2);
    cudaGetSymbolAddress(&p_xvec,      d_xvec);
    cudaGetSymbolAddress(&p_hid_h,     d_hid_h);
    cudaGetSymbolAddress(&p_whh_t,     d_whh_t);
    cudaGetSymbolAddress(&p_wih_t,     d_wih_t);
    cudaGetSymbolAddress(&p_gi_h,      d_gi_h);
    cudaGetSymbolAddress(&p_gh_h,      d_gh_h);
    cudaGetSymbolAddress(&p_tension,   d_tension);

    const int SMEM_BYTES = 3 * STAGE_H * 2;   // 61440
    cudaFuncSetAttribute(gemm_fp16,
                         cudaFuncAttributeMaxDynamicSharedMemorySize, SMEM_BYTES);

    init_kernel<<<64, 512>>>(bo, out);                                       // 1
    transpose_half<<<dim3(96, 32), dim3(32, 8)>>>(W_hh, (__half*)p_whh_t, 1024, 3072); // 2
    cvt_half<<<16384, 256>>>(hiddens, (__half*)p_hid_h);                     // 3

    // gh = hiddens @ W_hh + b_hh   [103 GF] -> fp16   (4th launch for ncu)
    gemm_fp16<<<dim3(24, 128), 256, SMEM_BYTES>>>(                           // 4
        (const __half*)p_hid_h, 1024, (const __half*)p_whh_t,
        nullptr, (__half*)p_gh_h, 3072, 1024, 8 | 16, b_hh, nullptr, nullptr);

    transpose_half<<<dim3(96, 16), dim3(32, 8)>>>(W_ih, (__half*)p_wih_t, 512, 3072);  // 5
    prep_kernel<<<16, 512>>>(x, Wa1, ba1, Wg1, bg1);                         // 6
    w1t_kernel<<<dim3(4, 256), 256>>>(Wa1, Wg1);                             // 7
    w2t_kernel<<<dim3(1, 512), 256>>>(Wa2, ba2, Wg2, bg2);                   // 8
    count_kernel<<<64, 256>>>(positions);                                    // 9

    // H1 = relu(hid @ W1 + xvec) -> fp16 only
    gemm_fp16<<<dim3(2, 128), 256, SMEM_BYTES>>>(                            // 10
        (const __half*)p_hid_h, 1024, (const __half*)p_w1t,
        nullptr, (__half*)p_srelu_h, 256, 1024, 1 | 8 | 16,
        (const float*)p_xvec, nullptr, nullptr);

    // soutput = H1 @ [Wa2;-Wg2] + bias2 -> fp16 only
    gemm_fp16<<<dim3(4, 128), 256, SMEM_BYTES>>>(                            // 11
        (const __half*)p_srelu_h, 256, (const __half*)p_w2t,
        nullptr, (__half*)p_soutput_h, 512, 256, 8 | 16,
        (const float*)p_bias2, nullptr, nullptr);

    tension_kernel<<<2048, 256>>>();                                         // 12
    sumexp_kernel<<<64, 256>>>();                                            // 13

    // gi = output @ W_ih[:512] + tension x W_ih[512] + b_ih  [51.5 GF] -> fp16
    gemm_fp16<<<dim3(24, 128), 256, SMEM_BYTES>>>(                           // 14
        (const __half*)p_soutput_h, 512, (const __half*)p_wih_t,
        nullptr, (__half*)p_gi_h, 3072, 512, 2 | 8 | 16, b_ih,
        (const float*)p_tension, W_ih + (size_t)512 * 3072);

    gru_kernel<<<32768, 256>>>(hiddens, wealth);                             // 15
    stats_kernel<<<dim3(8, 8, 8), 128>>>(positions);                         // 16
    statsfinal_kernel<<<1, 1024>>>();                                        // 17
    final_kernel<<<16384, 256>>>(positions, step, out);                      // 18
    wsum_kernel<<<256, 256>>>();                                             // 19
    pred_kernel<<<8, 512>>>(Wo, out);                                        // 20
}

// round 12
// speedup vs baseline: 1.1417x; 1.1417x over previous
#include <cuda_runtime.h>
#include <cuda_fp16.h>
#include <mma.h>
#include <math.h>
#include <stdint.h>

using namespace nvcuda;

#define N_CELLS 16384
#define D_IN    512
#define D_HID   1024
#define D_OUT   512
#define G3H     3072
#define NF      8
#define FS      2048
#define NBIG    3328   // 3072 (gh) + 256 (H1)

// ---------------- device scratch (static, allocation-free) ----------------
__device__ __half d_wbig[(size_t)NBIG * D_HID];        // [W_hh^T ; W1^T] K-major
__device__ float  d_biasbig[NBIG];                     // [b_hh | xvec]
__device__ __half d_w2t[512 * 256];                    // [N=512][K=256] ([Wa2;-Wg2]^T)
__device__ float  d_bias2[512];                        // ba2 - bg2
__device__ __half d_wih_t[(size_t)G3H * D_OUT];        // W_ih[:512]^T [3072][512]
__device__ __half d_hid_h[(size_t)N_CELLS * D_HID];    // fp16 hiddens
__device__ __half d_srelu_h[(size_t)N_CELLS * 256];    // fp16 relu acts (a|g)
__device__ __half d_soutput_h[(size_t)N_CELLS * 512];  // fp16 output = a - g
__device__ float  d_tension[N_CELLS];
__device__ float  d_ebuf[N_CELLS];
__device__ __half d_gi_h[(size_t)N_CELLS * G3H];       // fp16 gi preacts
__device__ __half d_gh_h[(size_t)N_CELLS * G3H];       // fp16 gh preacts
__device__ float  d_hpost[(size_t)N_CELLS * D_HID];
__device__ float  d_sumall[NF * D_HID];
__device__ float  d_sumpos[NF * D_HID];
__device__ float  d_sumneg[NF * D_HID];
__device__ float  d_meanp[D_HID];
__device__ float  d_meann[D_HID];
__device__ float  d_F[NF * D_HID];
__device__ float  d_gop[D_HID];
__device__ int    d_cntp[NF];
__device__ int    d_cntn[NF];
__device__ int    d_cnt_tot[2];
__device__ float  d_tsum;
__device__ float  d_sumexp;
__device__ int    d_tmax_i;
__device__ float  d_cout[512];

// ---------------- cp.async helpers ----------------
__device__ __forceinline__ void cp16(uint32_t daddr, const void* src) {
    asm volatile("cp.async.cg.shared.global [%0], [%1], 16;" :: "r"(daddr), "l"(src));
}
__device__ __forceinline__ void cp_commit() {
    asm volatile("cp.async.commit_group;" ::: "memory");
}
template <int N>
__device__ __forceinline__ void cp_wait() {
    asm volatile("cp.async.wait_group %0;" :: "n"(N) : "memory");
}

__device__ __forceinline__ float fast_sigmoid(float x) {
    return 1.0f / (1.0f + __expf(-x));
}
__device__ __forceinline__ float fast_tanh(float x) {
    float a = fabsf(x);
    float e = __expf(-2.0f * a);
    float r = (1.0f - e) / (1.0f + e);
    return copysignf(r, x);
}

// ---------------- pipelined fp16 WMMA GEMM (proven config) ----------------
// C[M x Ntot] = A[M x K] (fp16, row-major) * Bt[Ntot x K] (fp16, K-major)^T
// Block tile 128x128, BK=32, 3-stage cp.async pipeline, 256 threads,
// warp grid 2x4 (warp tile 64x32), fp32 accumulate, 2 CTAs/SM.
// modes: 1=relu, 2=+rowv[m]*colv[n], 8=write half Ch, 16=skip fp32 C,
//        4=fused gh+H1 epilogue (cols<3072 -> d_gh_h, cols>=3072 -> relu d_srelu_h)
#define STAGE_H 10240   // halves per stage: A 128x40 + B 128x40

__global__ void __launch_bounds__(256, 2) gemm_fp16(
    const __half* __restrict__ A, int lda,
    const __half* __restrict__ Bt,
    float* __restrict__ C, __half* __restrict__ Ch, int ldc,
    int K, int mode,
    const float* __restrict__ bias,
    const float* __restrict__ rowv,
    const float* __restrict__ colv)
{
    extern __shared__ __align__(16) char smem_raw[];
    __half* smem = (__half*)smem_raw;
    const uint32_t sbase = (uint32_t)__cvta_generic_to_shared(smem);

    const int tid  = threadIdx.x;
    const int bm   = blockIdx.y * 128;
    const int bn   = blockIdx.x * 128;
    const int warp = tid >> 5;
    const int wr   = warp & 1;   // 2 warp rows of 64
    const int wc   = warp >> 1;  // 4 warp cols of 32

    wmma::fragment<wmma::accumulator, 16, 16, 16, float> acc[4][2];
#pragma unroll
    for (int i = 0; i < 4; i++)
#pragma unroll
        for (int j = 0; j < 2; j++) wmma::fill_fragment(acc[i][j], 0.0f);

    const int crow = tid >> 1;           // 0..127
    const int ccol = (tid & 1) << 4;     // 0 or 16 (halves)

#define ISSUE(KT)                                                              \
    {                                                                          \
        uint32_t so = ((KT) % 3) * STAGE_H;                                    \
        int k0 = (KT) << 5;                                                    \
        _Pragma("unroll")                                                      \
        for (int h2 = 0; h2 < 2; h2++) {                                       \
            int cc = ccol + h2 * 8;                                            \
            cp16(sbase + (so + crow * 40 + cc) * 2,                            \
                 A + (size_t)(bm + crow) * lda + k0 + cc);                     \
            cp16(sbase + (so + 5120 + crow * 40 + cc) * 2,                     \
                 Bt + (size_t)(bn + crow) * K + k0 + cc);                      \
        }                                                                      \
        cp_commit();                                                           \
    }

#define MMA_TILE(KT)                                                           \
    {                                                                          \
        __half* As = smem + ((KT) % 3) * STAGE_H;                              \
        __half* Bs = As + 5120;                                                \
        _Pragma("unroll")                                                      \
        for (int kk = 0; kk < 32; kk += 16) {                                  \
            wmma::fragment<wmma::matrix_a, 16, 16, 16, __half, wmma::row_major> af[4]; \
            wmma::fragment<wmma::matrix_b, 16, 16, 16, __half, wmma::col_major> bf[2]; \
            _Pragma("unroll")                                                  \
            for (int i = 0; i < 4; i++)                                        \
                wmma::load_matrix_sync(af[i], As + (wr * 64 + i * 16) * 40 + kk, 40); \
            _Pragma("unroll")                                                  \
            for (int j = 0; j < 2; j++)                                        \
                wmma::load_matrix_sync(bf[j], Bs + (wc * 32 + j * 16) * 40 + kk, 40); \
            _Pragma("unroll")                                                  \
            for (int i = 0; i < 4; i++)                                        \
                _Pragma("unroll")                                              \
                for (int j = 0; j < 2; j++)                                    \
                    wmma::mma_sync(acc[i][j], af[i], bf[j], acc[i][j]);        \
        }                                                                      \
    }

    const int nk = K >> 5;
    ISSUE(0)
    ISSUE(1)

    for (int kt = 0; kt < nk - 1; kt++) {
        cp_wait<1>();
        __syncthreads();
        if (kt + 2 < nk) ISSUE(kt + 2)
        MMA_TILE(kt)
    }
    cp_wait<0>();
    __syncthreads();
    MMA_TILE(nk - 1)
#undef ISSUE
#undef MMA_TILE

    // epilogue in two 64-col halves staged through shared (floats, stride 72)
    float* Cs = (float*)smem;
#pragma unroll
    for (int h = 0; h < 2; h++) {
        __syncthreads();
        if ((wc >> 1) == h) {
            const int lc = (wc & 1) << 5;
#pragma unroll
            for (int i = 0; i < 4; i++)
#pragma unroll
                for (int j = 0; j < 2; j++)
                    wmma::store_matrix_sync(Cs + (wr * 64 + i * 16) * 72 + lc + j * 16,
                                            acc[i][j], 72, wmma::mem_row_major);
        }
        __syncthreads();
#pragma unroll
        for (int it = 0; it < 32; it++) {
            int idx = it * 256 + tid;
            int r = idx >> 6, c = idx & 63;
            int gr = bm + r, gc = bn + (h << 6) + c;
            float v = Cs[r * 72 + c] + bias[gc];
            if (mode & 4) {
                // fused gh + H1 epilogue
                if (gc < G3H) d_gh_h[(size_t)gr * G3H + gc] = __float2half(v);
                else d_srelu_h[(size_t)gr * 256 + (gc - G3H)] =
                         __float2half(fmaxf(v, 0.0f));
            } else {
                if (mode & 2) v += rowv[gr] * colv[gc];
                if (mode & 1) v = fmaxf(v, 0.0f);
                if (!(mode & 16)) C[(size_t)gr * ldc + gc] = v;
                if (mode & 8)  Ch[(size_t)gr * ldc + gc] = __float2half(v);
            }
        }
    }
}

// ---------------- prep kernels ----------------
__global__ void cvt_half(const float* __restrict__ src, __half* __restrict__ dst) {
    size_t i = (size_t)blockIdx.x * 256 + threadIdx.x;
    float4 v = reinterpret_cast<const float4*>(src)[i];
    __half2* d = reinterpret_cast<__half2*>(dst) + i * 2;
    d[0] = __floats2half2_rn(v.x, v.y);
    d[1] = __floats2half2_rn(v.z, v.w);
}

// dst[(c)*dstStride + r] = (half)src[r][c]; src R x Ccols
__global__ void transpose_half(const float* __restrict__ src, __half* __restrict__ dst,
                               int R, int Ccols) {
    __shared__ float tile[32][33];
    int c0 = blockIdx.x * 32, r0 = blockIdx.y * 32;
    int x = threadIdx.x, y = threadIdx.y;   // (32, 8)
#pragma unroll
    for (int i = 0; i < 32; i += 8)
        tile[y + i][x] = src[(size_t)(r0 + y + i) * Ccols + c0 + x];
    __syncthreads();
#pragma unroll
    for (int i = 0; i < 32; i += 8)
        dst[(size_t)(c0 + y + i) * R + r0 + x] = __float2half(tile[x][y + i]);
}

// W1^T into wbig rows 3072..3327 (K-major, stride 1024)
__global__ void w1t_kernel(const float* __restrict__ Wa1, const float* __restrict__ Wg1) {
    int n = blockIdx.y;                         // 0..255
    int k = blockIdx.x * 256 + threadIdx.x;     // 0..1023
    float v = (n < 128) ? Wa1[(size_t)(512 + k) * 128 + n]
                        : Wg1[(size_t)(512 + k) * 128 + (n - 128)];
    d_wbig[(size_t)(G3H + n) * 1024 + k] = __float2half(v);
}

__global__ void w2t_kernel(const float* __restrict__ Wa2, const float* __restrict__ ba2,
                           const float* __restrict__ Wg2, const float* __restrict__ bg2) {
    int n = blockIdx.y;                // 0..511
    int k = threadIdx.x;               // 0..255
    float v = (k < 128) ? Wa2[(size_t)k * 512 + n] : -Wg2[(size_t)(k - 128) * 512 + n];
    d_w2t[n * 256 + k] = __float2half(v);
    if (k == 0) d_bias2[n] = ba2[n] - bg2[n];
}

// init: zero accumulators, seed out with bo, copy b_hh into biasbig
__global__ void init_kernel(const float* __restrict__ bo, const float* __restrict__ b_hh,
                            float* __restrict__ out) {
    int gid = blockIdx.x * 512 + threadIdx.x;   // grid 64 x 512 = 32768
    if (gid < NF * D_HID) {
        d_sumall[gid] = 0.0f; d_sumpos[gid] = 0.0f; d_sumneg[gid] = 0.0f;
    }
    if (gid < G3H) d_biasbig[gid] = b_hh[gid];
    if (gid < 512) { d_cout[gid] = 0.0f; out[gid] = bo[gid]; }
    if (gid >= 512 && gid < 512 + NF) { d_cntp[gid - 512] = 0; d_cntn[gid - 512] = 0; }
    if (gid == 0) { d_tsum = 0.0f; d_sumexp = 0.0f; d_tmax_i = 0; }
}

__global__ void count_kernel(const int* __restrict__ pos) {
    int i = blockIdx.x * 256 + threadIdx.x;
    int p = pos[i];
    int f = i >> 11;
    if (p > 0) atomicAdd(&d_cntp[f], 1);
    else if (p < 0) atomicAdd(&d_cntn[f], 1);
}

// warp-per-column GEMV: biasbig[3072+n] = b1[n] + sum_k x[k]*W1[k][n]
__global__ void prep_kernel(const float* __restrict__ x,
                            const float* __restrict__ Wa1, const float* __restrict__ ba1,
                            const float* __restrict__ Wg1, const float* __restrict__ bg1) {
    int n = (blockIdx.x << 4) + (threadIdx.x >> 5);  // grid 16 x 512 -> n 0..255
    int lane = threadIdx.x & 31;
    const float* W = (n < 128) ? Wa1 : Wg1;
    int col = n & 127;
    float s = 0.0f;
    for (int k = lane; k < D_IN; k += 32) s += x[k] * W[k * 128 + col];
#pragma unroll
    for (int off = 16; off; off >>= 1) s += __shfl_xor_sync(0xffffffffu, s, off);
    if (lane == 0) d_biasbig[G3H + n] = s + ((n < 128) ? ba1[col] : bg1[col]);
}

// ---------------- elementwise / reduction kernels ----------------
__global__ void tension_kernel() {
    int row  = blockIdx.x * 8 + (threadIdx.x >> 5);
    int lane = threadIdx.x & 31;
    const __half2* o = reinterpret_cast<const __half2*>(d_soutput_h + (size_t)row * 512);
    float s = 0.0f;
    for (int c = lane; c < 256; c += 32) {
        float2 v = __half22float2(o[c]);
        s += v.x * v.x + v.y * v.y;
    }
#pragma unroll
    for (int off = 16; off; off >>= 1) s += __shfl_xor_sync(0xffffffffu, s, off);
    __shared__ float wsum[8];
    __shared__ float wmax[8];
    float t = s * (1.0f / 512.0f);
    if (lane == 0) {
        d_tension[row] = t;
        wsum[threadIdx.x >> 5] = t;
        wmax[threadIdx.x >> 5] = t;
    }
    __syncthreads();
    if (threadIdx.x == 0) {
        float a = 0.0f, m = 0.0f;
        for (int w = 0; w < 8; w++) { a += wsum[w]; m = fmaxf(m, wmax[w]); }
        atomicAdd(&d_tsum, a);
        atomicMax(&d_tmax_i, __float_as_int(m));   // tension >= 0, int cmp ok
    }
}

__global__ void sumexp_kernel() {
    int i = blockIdx.x * 256 + threadIdx.x;
    float tmax = __int_as_float(d_tmax_i);
    float e = __expf(d_tension[i] - tmax);
    d_ebuf[i] = e;
    __shared__ float sh[256];
    sh[threadIdx.x] = e;
    __syncthreads();
    for (int s = 128; s; s >>= 1) {
        if (threadIdx.x < s) sh[threadIdx.x] += sh[threadIdx.x + s];
        __syncthreads();
    }
    if (threadIdx.x == 0) atomicAdd(&d_sumexp, sh[0]);
}

// GRU combine + wealth mod + clip; half2 vectorized (2 elems/thread)
__global__ void gru_kernel(const float* __restrict__ hid, const float* __restrict__ wealth) {
    size_t t = (size_t)blockIdx.x * 256 + threadIdx.x;   // 0 .. 8.39M
    int i  = (int)(t >> 9);          // row
    int j2 = (int)(t & 511);         // half2 index within 1024-wide row
    const __half2* gi = reinterpret_cast<const __half2*>(d_gi_h + (size_t)i * G3H);
    const __half2* gh = reinterpret_cast<const __half2*>(d_gh_h + (size_t)i * G3H);
    float2 gir = __half22float2(gi[j2]);
    float2 giz = __half22float2(gi[j2 + 512]);
    float2 gin = __half22float2(gi[j2 + 1024]);
    float2 ghr = __half22float2(gh[j2]);
    float2 ghz = __half22float2(gh[j2 + 512]);
    float2 ghn = __half22float2(gh[j2 + 1024]);
    float2 h = *reinterpret_cast<const float2*>(hid + (size_t)i * 1024 + j2 * 2);
    float w = wealth[i];
    float mod = 0.9f + 0.1f * fminf(fmaxf(w, 0.1f), 2.0f);

    float r0 = fast_sigmoid(gir.x + ghr.x);
    float z0 = fast_sigmoid(giz.x + ghz.x);
    float n0 = fast_tanh(gin.x + r0 * ghn.x);
    float nh0 = fminf(fmaxf(((1.0f - z0) * n0 + z0 * h.x) * mod, -10.0f), 10.0f);

    float r1 = fast_sigmoid(gir.y + ghr.y);
    float z1 = fast_sigmoid(giz.y + ghz.y);
    float n1 = fast_tanh(gin.y + r1 * ghn.y);
    float nh1 = fminf(fmaxf(((1.0f - z1) * n1 + z1 * h.y) * mod, -10.0f), 10.0f);

    *reinterpret_cast<float2*>(d_hpost + (size_t)i * 1024 + j2 * 2) = make_float2(nh0, nh1);
}

// per-faction column sums, row-chunked: grid (8, 8, 8)
__global__ void stats_kernel(const int* __restrict__ pos) {
    int f = blockIdx.x;                          // faction
    int j = blockIdx.y * 128 + threadIdx.x;      // column
    int r0 = blockIdx.z * 256;                   // row chunk within faction
    int base = f * FS + r0;
    float sa = 0.0f, sp = 0.0f, sn = 0.0f;
    for (int r = 0; r < 256; r++) {
        float v = d_hpost[(size_t)(base + r) * D_HID + j];
        int p = pos[base + r];
        sa += v;
        if (p > 0) sp += v; else if (p < 0) sn += v;
    }
    atomicAdd(&d_sumall[f * D_HID + j], sa);
    atomicAdd(&d_sumpos[f * D_HID + j], sp);
    atomicAdd(&d_sumneg[f * D_HID + j], sn);
}

__global__ void statsfinal_kernel() {
    int j = threadIdx.x;           // 0..1023
    int cp = 0, cn = 0;
    for (int f = 0; f < NF; f++) { cp += d_cntp[f]; cn += d_cntn[f]; }
    float sp = 0.0f, sn = 0.0f;
    for (int f = 0; f < NF; f++) { sp += d_sumpos[f * D_HID + j]; sn += d_sumneg[f * D_HID + j]; }
    float mp = sp / (float)max(cp, 1);
    float mn = sn / (float)max(cn, 1);
    d_meanp[j] = mp; d_meann[j] = mn;
    float g = 0.0f;
    for (int f = 0; f < NF; f++) {
        float adj = d_sumall[f * D_HID + j];
        if (cp >= 2) adj += 0.1f * ((float)d_cntp[f] * mp - d_sumpos[f * D_HID + j]);
        if (cn >= 2) adj += 0.1f * ((float)d_cntn[f] * mn - d_sumneg[f * D_HID + j]);
        float F = adj * (1.0f / (float)FS);
        d_F[f * D_HID + j] = F;
        g += F;
    }
    d_gop[j] = g * (1.0f / (float)NF);
    if (j == 0) { d_cnt_tot[0] = cp; d_cnt_tot[1] = cn; }
}

// apply syncs + debate; float4 per thread
__global__ void final_kernel(const int* __restrict__ pos, const int* __restrict__ step,
                             float* __restrict__ out) {
    size_t t = (size_t)blockIdx.x * 256 + threadIdx.x;   // 0 .. 4.19M
    int i = (int)(t >> 8);
    int j = (int)(t & 255) * 4;
    float4 h4 = *reinterpret_cast<const float4*>(d_hpost + (size_t)i * 1024 + j);
    int p = pos[i];
    int cp = d_cnt_tot[0], cn = d_cnt_tot[1];
    float* hv = (float*)&h4;
    if (p > 0 && cp >= 2) {
        const float4 m4 = *reinterpret_cast<const float4*>(d_meanp + j);
        const float* mv = (const float*)&m4;
#pragma unroll
        for (int q = 0; q < 4; q++) hv[q] = 0.9f * hv[q] + 0.1f * mv[q];
    } else if (p < 0 && cn >= 2) {
        const float4 m4 = *reinterpret_cast<const float4*>(d_meann + j);
        const float* mv = (const float*)&m4;
#pragma unroll
        for (int q = 0; q < 4; q++) hv[q] = 0.9f * hv[q] + 0.1f * mv[q];
    }
    int f = i >> 11;
    const float4 F4 = *reinterpret_cast<const float4*>(d_F + f * D_HID + j);
    const float* Fv = (const float*)&F4;
#pragma unroll
    for (int q = 0; q < 4; q++) hv[q] = 0.85f * hv[q] + 0.15f * Fv[q];
    if (*step > 5 && (i & (FS - 1)) < (FS / 4)) {
        const float4 g4 = *reinterpret_cast<const float4*>(d_gop + j);
        const float* gv = (const float*)&g4;
#pragma unroll
        for (int q = 0; q < 4; q++) hv[q] = 0.85f * hv[q] + 0.15f * gv[q];
    }
    float* o = out + 513 + (size_t)i * 1024 + j;
#pragma unroll
    for (int q = 0; q < 4; q++) o[q] = hv[q];
}

// combined_out = sum_i softmax(tension)_i * output[i,:]; 256 blocks x 64 rows
__global__ void wsum_kernel() {
    int r0 = blockIdx.x * 64;
    float inv = 1.0f / d_sumexp;
    int t = threadIdx.x;
    float c0 = 0.0f, c1 = 0.0f;
    for (int r = r0; r < r0 + 64; r++) {
        float w = d_ebuf[r] * inv;
        const __half* o = d_soutput_h + (size_t)r * 512;
        c0 += w * __half2float(o[t]);
        c1 += w * __half2float(o[t + 256]);
    }
    atomicAdd(&d_cout[t], c0);
    atomicAdd(&d_cout[t + 256], c1);
}

// split-K GEMV: out[t] += sum_{k in chunk} cout[k]*Wo[k][t]; bias seeded in init
__global__ void pred_kernel(const float* __restrict__ Wo, float* __restrict__ out) {
    __shared__ float co[64];
    int b = blockIdx.x;      // 0..7
    int t = threadIdx.x;     // 0..511
    if (t < 64) co[t] = d_cout[b * 64 + t];
    __syncthreads();
    float s = 0.0f;
#pragma unroll 8
    for (int k = 0; k < 64; k++) s += co[k] * Wo[(size_t)(b * 64 + k) * 512 + t];
    atomicAdd(&out[t], s);
    if (b == 0 && t == 0) out[512] = d_tsum * (1.0f / (float)N_CELLS);
}

// ---------------- launch ----------------
extern "C" void kernel_launch(void* const* d_in, const int* in_sizes, int n_in,
                              void* d_out, int out_size) {
    const float* x        = (const float*)d_in[0];
    const float* hiddens  = (const float*)d_in[1];
    const float* wealth   = (const float*)d_in[2];
    const float* Wa1      = (const float*)d_in[3];
    const float* ba1      = (const float*)d_in[4];
    const float* Wa2      = (const float*)d_in[5];
    const float* ba2      = (const float*)d_in[6];
    const float* Wg1      = (const float*)d_in[7];
    const float* bg1      = (const float*)d_in[8];
    const float* Wg2      = (const float*)d_in[9];
    const float* bg2      = (const float*)d_in[10];
    const float* W_ih     = (const float*)d_in[11];
    const float* W_hh     = (const float*)d_in[12];
    const float* b_ih     = (const float*)d_in[13];
    const float* b_hh     = (const float*)d_in[14];
    const float* Wo       = (const float*)d_in[15];
    const float* bo       = (const float*)d_in[16];
    const int*   positions= (const int*)d_in[17];
    const int*   step     = (const int*)d_in[18];
    float* out = (float*)d_out;

    void *p_srelu_h, *p_soutput_h, *p_w2t, *p_bias2, *p_wbig, *p_biasbig;
    void *p_hid_h, *p_wih_t, *p_gi_h, *p_gh_h, *p_tension;
    cudaGetSymbolAddress(&p_srelu_h,   d_srelu_h);
    cudaGetSymbolAddress(&p_soutput_h, d_soutput_h);
    cudaGetSymbolAddress(&p_w2t,       d_w2t);
    cudaGetSymbolAddress(&p_bias2,     d_bias2);
    cudaGetSymbolAddress(&p_wbig,      d_wbig);
    cudaGetSymbolAddress(&p_biasbig,   d_biasbig);
    cudaGetSymbolAddress(&p_hid_h,     d_hid_h);
    cudaGetSymbolAddress(&p_wih_t,     d_wih_t);
    cudaGetSymbolAddress(&p_gi_h,      d_gi_h);
    cudaGetSymbolAddress(&p_gh_h,      d_gh_h);
    cudaGetSymbolAddress(&p_tension,   d_tension);

    const int SMEM_BYTES = 3 * STAGE_H * 2;   // 61440
    cudaFuncSetAttribute(gemm_fp16,
                         cudaFuncAttributeMaxDynamicSharedMemorySize, SMEM_BYTES);

    init_kernel<<<64, 512>>>(bo, b_hh, out);                                 // 1
    transpose_half<<<dim3(96, 32), dim3(32, 8)>>>(W_hh, (__half*)p_wbig, 1024, 3072); // 2
    cvt_half<<<16384, 256>>>(hiddens, (__half*)p_hid_h);                     // 3
    w1t_kernel<<<dim3(4, 256), 256>>>(Wa1, Wg1);                             // 4
    prep_kernel<<<16, 512>>>(x, Wa1, ba1, Wg1, bg1);                         // 5

    // fused: [gh | H1] = hid @ [W_hh | W1] + [b_hh | xvec]  [112 GF]
    gemm_fp16<<<dim3(26, 128), 256, SMEM_BYTES>>>(                           // 6
        (const __half*)p_hid_h, 1024, (const __half*)p_wbig,
        nullptr, nullptr, 0, 1024, 4,
        (const float*)p_biasbig, nullptr, nullptr);

    transpose_half<<<dim3(96, 16), dim3(32, 8)>>>(W_ih, (__half*)p_wih_t, 512, 3072);  // 7
    w2t_kernel<<<dim3(1, 512), 256>>>(Wa2, ba2, Wg2, bg2);                   // 8
    count_kernel<<<64, 256>>>(positions);                                    // 9

    // soutput = H1 @ [Wa2;-Wg2] + bias2 -> fp16 only
    gemm_fp16<<<dim3(4, 128), 256, SMEM_BYTES>>>(                            // 10
        (const __half*)p_srelu_h, 256, (const __half*)p_w2t,
        nullptr, (__half*)p_soutput_h, 512, 256, 8 | 16,
        (const float*)p_bias2, nullptr, nullptr);

    tension_kernel<<<2048, 256>>>();                                         // 11
    sumexp_kernel<<<64, 256>>>();                                            // 12

    // gi = output @ W_ih[:512] + tension x W_ih[512] + b_ih  [51.5 GF] -> fp16
    gemm_fp16<<<dim3(24, 128), 256, SMEM_BYTES>>>(                           // 13
        (const __half*)p_soutput_h, 512, (const __half*)p_wih_t,
        nullptr, (__half*)p_gi_h, 3072, 512, 2 | 8 | 16, b_ih,
        (const float*)p_tension, W_ih + (size_t)512 * 3072);

    gru_kernel<<<32768, 256>>>(hiddens, wealth);                             // 14
    stats_kernel<<<dim3(8, 8, 8), 128>>>(positions);                         // 15
    statsfinal_kernel<<<1, 1024>>>();                                        // 16
    final_kernel<<<16384, 256>>>(positions, step, out);                      // 17
    wsum_kernel<<<256, 256>>>();                                             // 18
    pred_kernel<<<8, 512>>>(Wo, out);                                        // 19
}

// round 13
// speedup vs baseline: 1.1854x; 1.0382x over previous
#include <cuda_runtime.h>
#include <cuda_fp16.h>
#include <mma.h>
#include <math.h>
#include <stdint.h>

using namespace nvcuda;

#define N_CELLS 16384
#define D_IN    512
#define D_HID   1024
#define D_OUT   512
#define G3H     3072
#define NF      8
#define FS      2048
#define NBIG    3328   // 3072 (gh) + 256 (H1)

// ---------------- device scratch (static, allocation-free) ----------------
__device__ __half d_wbig[(size_t)NBIG * D_HID];        // [W_hh^T ; W1^T] K-major
__device__ float  d_biasbig[NBIG];                     // [b_hh | xvec]
__device__ __half d_w2t[512 * 256];                    // [N=512][K=256] ([Wa2;-Wg2]^T)
__device__ __half d_w2h[256 * 512];                    // [M=256][K=512] W2cat row-major
__device__ float  d_bias2[512];                        // ba2 - bg2
__device__ __half d_wih_t[(size_t)G3H * D_OUT];        // W_ih[:512]^T [3072][512]
__device__ __half d_w2wt[(size_t)G3H * 256];           // (W2cat@W_ih)^T [3072][256]
__device__ float  d_beff[G3H];                         // b_ih + bias2@W_ih
__device__ __half d_hid_h[(size_t)N_CELLS * D_HID];    // fp16 hiddens
__device__ __half d_srelu_h[(size_t)N_CELLS * 256];    // fp16 relu acts (a|g)
__device__ __half d_soutput_h[(size_t)N_CELLS * 512];  // fp16 output = a - g
__device__ float  d_tension[N_CELLS];
__device__ float  d_ebuf[N_CELLS];
__device__ __half d_gi_h[(size_t)N_CELLS * G3H];       // fp16 gi preacts
__device__ __half d_gh_h[(size_t)N_CELLS * G3H];       // fp16 gh preacts
__device__ float  d_hpost[(size_t)N_CELLS * D_HID];
__device__ float  d_sumall[NF * D_HID];
__device__ float  d_sumpos[NF * D_HID];
__device__ float  d_sumneg[NF * D_HID];
__device__ float  d_meanp[D_HID];
__device__ float  d_meann[D_HID];
__device__ float  d_F[NF * D_HID];
__device__ float  d_gop[D_HID];
__device__ int    d_cntp[NF];
__device__ int    d_cntn[NF];
__device__ int    d_cnt_tot[2];
__device__ float  d_tsum;
__device__ float  d_sumexp;
__device__ int    d_tmax_i;
__device__ float  d_cout[512];

// ---------------- cp.async helpers ----------------
__device__ __forceinline__ void cp16(uint32_t daddr, const void* src) {
    asm volatile("cp.async.cg.shared.global [%0], [%1], 16;" :: "r"(daddr), "l"(src));
}
__device__ __forceinline__ void cp_commit() {
    asm volatile("cp.async.commit_group;" ::: "memory");
}
template <int N>
__device__ __forceinline__ void cp_wait() {
    asm volatile("cp.async.wait_group %0;" :: "n"(N) : "memory");
}

__device__ __forceinline__ float fast_sigmoid(float x) {
    return 1.0f / (1.0f + __expf(-x));
}
__device__ __forceinline__ float fast_tanh(float x) {
    float a = fabsf(x);
    float e = __expf(-2.0f * a);
    float r = (1.0f - e) / (1.0f + e);
    return copysignf(r, x);
}

// ---------------- pipelined fp16 WMMA GEMM (proven config) ----------------
// C[M x Ntot] = A[M x K] (fp16, row-major) * Bt[Ntot x K] (fp16, K-major)^T
// Block tile 128x128, BK=32, 3-stage cp.async pipeline, 256 threads,
// warp grid 2x4 (warp tile 64x32), fp32 accumulate, 2 CTAs/SM.
// modes: 1=relu, 2=+rowv[m]*colv[n], 8=write half Ch, 16=skip fp32 C,
//        4=fused gh+H1 epilogue, 32=no bias
#define STAGE_H 10240   // halves per stage: A 128x40 + B 128x40

__global__ void __launch_bounds__(256, 2) gemm_fp16(
    const __half* __restrict__ A, int lda,
    const __half* __restrict__ Bt,
    float* __restrict__ C, __half* __restrict__ Ch, int ldc,
    int K, int mode,
    const float* __restrict__ bias,
    const float* __restrict__ rowv,
    const float* __restrict__ colv)
{
    extern __shared__ __align__(16) char smem_raw[];
    __half* smem = (__half*)smem_raw;
    const uint32_t sbase = (uint32_t)__cvta_generic_to_shared(smem);

    const int tid  = threadIdx.x;
    const int bm   = blockIdx.y * 128;
    const int bn   = blockIdx.x * 128;
    const int warp = tid >> 5;
    const int wr   = warp & 1;   // 2 warp rows of 64
    const int wc   = warp >> 1;  // 4 warp cols of 32

    wmma::fragment<wmma::accumulator, 16, 16, 16, float> acc[4][2];
#pragma unroll
    for (int i = 0; i < 4; i++)
#pragma unroll
        for (int j = 0; j < 2; j++) wmma::fill_fragment(acc[i][j], 0.0f);

    const int crow = tid >> 1;           // 0..127
    const int ccol = (tid & 1) << 4;     // 0 or 16 (halves)

#define ISSUE(KT)                                                              \
    {                                                                          \
        uint32_t so = ((KT) % 3) * STAGE_H;                                    \
        int k0 = (KT) << 5;                                                    \
        _Pragma("unroll")                                                      \
        for (int h2 = 0; h2 < 2; h2++) {                                       \
            int cc = ccol + h2 * 8;                                            \
            cp16(sbase + (so + crow * 40 + cc) * 2,                            \
                 A + (size_t)(bm + crow) * lda + k0 + cc);                     \
            cp16(sbase + (so + 5120 + crow * 40 + cc) * 2,                     \
                 Bt + (size_t)(bn + crow) * K + k0 + cc);                      \
        }                                                                      \
        cp_commit();                                                           \
    }

#define MMA_TILE(KT)                                                           \
    {                                                                          \
        __half* As = smem + ((KT) % 3) * STAGE_H;                              \
        __half* Bs = As + 5120;                                                \
        _Pragma("unroll")                                                      \
        for (int kk = 0; kk < 32; kk += 16) {                                  \
            wmma::fragment<wmma::matrix_a, 16, 16, 16, __half, wmma::row_major> af[4]; \
            wmma::fragment<wmma::matrix_b, 16, 16, 16, __half, wmma::col_major> bf[2]; \
            _Pragma("unroll")                                                  \
            for (int i = 0; i < 4; i++)                                        \
                wmma::load_matrix_sync(af[i], As + (wr * 64 + i * 16) * 40 + kk, 40); \
            _Pragma("unroll")                                                  \
            for (int j = 0; j < 2; j++)                                        \
                wmma::load_matrix_sync(bf[j], Bs + (wc * 32 + j * 16) * 40 + kk, 40); \
            _Pragma("unroll")                                                  \
            for (int i = 0; i < 4; i++)                                        \
                _Pragma("unroll")                                              \
                for (int j = 0; j < 2; j++)                                    \
                    wmma::mma_sync(acc[i][j], af[i], bf[j], acc[i][j]);        \
        }                                                                      \
    }

    const int nk = K >> 5;
    ISSUE(0)
    ISSUE(1)

    for (int kt = 0; kt < nk - 1; kt++) {
        cp_wait<1>();
        __syncthreads();
        if (kt + 2 < nk) ISSUE(kt + 2)
        MMA_TILE(kt)
    }
    cp_wait<0>();
    __syncthreads();
    MMA_TILE(nk - 1)
#undef ISSUE
#undef MMA_TILE

    // epilogue in two 64-col halves staged through shared (floats, stride 72)
    float* Cs = (float*)smem;
#pragma unroll
    for (int h = 0; h < 2; h++) {
        __syncthreads();
        if ((wc >> 1) == h) {
            const int lc = (wc & 1) << 5;
#pragma unroll
            for (int i = 0; i < 4; i++)
#pragma unroll
                for (int j = 0; j < 2; j++)
                    wmma::store_matrix_sync(Cs + (wr * 64 + i * 16) * 72 + lc + j * 16,
                                            acc[i][j], 72, wmma::mem_row_major);
        }
        __syncthreads();
#pragma unroll
        for (int it = 0; it < 32; it++) {
            int idx = it * 256 + tid;
            int r = idx >> 6, c = idx & 63;
            int gr = bm + r, gc = bn + (h << 6) + c;
            float v = Cs[r * 72 + c];
            if (!(mode & 32)) v += bias[gc];
            if (mode & 4) {
                // fused gh + H1 epilogue
                if (gc < G3H) d_gh_h[(size_t)gr * G3H + gc] = __float2half(v);
                else d_srelu_h[(size_t)gr * 256 + (gc - G3H)] =
                         __float2half(fmaxf(v, 0.0f));
            } else {
                if (mode & 2) v += rowv[gr] * colv[gc];
                if (mode & 1) v = fmaxf(v, 0.0f);
                if (!(mode & 16)) C[(size_t)gr * ldc + gc] = v;
                if (mode & 8)  Ch[(size_t)gr * ldc + gc] = __float2half(v);
            }
        }
    }
}

// ---------------- prep kernels ----------------
__global__ void cvt_half(const float* __restrict__ src, __half* __restrict__ dst) {
    size_t i = (size_t)blockIdx.x * 256 + threadIdx.x;
    float4 v = reinterpret_cast<const float4*>(src)[i];
    __half2* d = reinterpret_cast<__half2*>(dst) + i * 2;
    d[0] = __floats2half2_rn(v.x, v.y);
    d[1] = __floats2half2_rn(v.z, v.w);
}

// dst[(c)*dstStride + r] = (half)src[r][c]; src R x Ccols
__global__ void transpose_half(const float* __restrict__ src, __half* __restrict__ dst,
                               int R, int Ccols) {
    __shared__ float tile[32][33];
    int c0 = blockIdx.x * 32, r0 = blockIdx.y * 32;
    int x = threadIdx.x, y = threadIdx.y;   // (32, 8)
#pragma unroll
    for (int i = 0; i < 32; i += 8)
        tile[y + i][x] = src[(size_t)(r0 + y + i) * Ccols + c0 + x];
    __syncthreads();
#pragma unroll
    for (int i = 0; i < 32; i += 8)
        dst[(size_t)(c0 + y + i) * R + r0 + x] = __float2half(tile[x][y + i]);
}

// W1^T into wbig rows 3072..3327 (K-major, stride 1024)
__global__ void w1t_kernel(const float* __restrict__ Wa1, const float* __restrict__ Wg1) {
    int n = blockIdx.y;                         // 0..255
    int k = blockIdx.x * 256 + threadIdx.x;     // 0..1023
    float v = (n < 128) ? Wa1[(size_t)(512 + k) * 128 + n]
                        : Wg1[(size_t)(512 + k) * 128 + (n - 128)];
    d_wbig[(size_t)(G3H + n) * 1024 + k] = __float2half(v);
}

__global__ void w2t_kernel(const float* __restrict__ Wa2, const float* __restrict__ ba2,
                           const float* __restrict__ Wg2, const float* __restrict__ bg2) {
    int n = blockIdx.y;                // 0..511
    int k = threadIdx.x;               // 0..255
    float v = (k < 128) ? Wa2[(size_t)k * 512 + n] : -Wg2[(size_t)(k - 128) * 512 + n];
    d_w2t[n * 256 + k] = __float2half(v);
    d_w2h[(size_t)k * 512 + n] = __float2half(v);
    if (k == 0) d_bias2[n] = ba2[n] - bg2[n];
}

// beff[c] = b_ih[c] + sum_o bias2[o] * W_ih[o][c]   (warp per c)
__global__ void beff_kernel(const float* __restrict__ b_ih) {
    int c = (blockIdx.x << 3) + (threadIdx.x >> 5);   // grid 384 x 256 -> c 0..3071
    int lane = threadIdx.x & 31;
    const __half* w = d_wih_t + (size_t)c * 512;
    float s = 0.0f;
    for (int o = lane; o < 512; o += 32) s += d_bias2[o] * __half2float(w[o]);
#pragma unroll
    for (int off = 16; off; off >>= 1) s += __shfl_xor_sync(0xffffffffu, s, off);
    if (lane == 0) d_beff[c] = s + b_ih[c];
}

// init: zero accumulators, seed out with bo, copy b_hh into biasbig
__global__ void init_kernel(const float* __restrict__ bo, const float* __restrict__ b_hh,
                            float* __restrict__ out) {
    int gid = blockIdx.x * 512 + threadIdx.x;   // grid 64 x 512 = 32768
    if (gid < NF * D_HID) {
        d_sumall[gid] = 0.0f; d_sumpos[gid] = 0.0f; d_sumneg[gid] = 0.0f;
    }
    if (gid < G3H) d_biasbig[gid] = b_hh[gid];
    if (gid < 512) { d_cout[gid] = 0.0f; out[gid] = bo[gid]; }
    if (gid >= 512 && gid < 512 + NF) { d_cntp[gid - 512] = 0; d_cntn[gid - 512] = 0; }
    if (gid == 0) { d_tsum = 0.0f; d_sumexp = 0.0f; d_tmax_i = 0; }
}

__global__ void count_kernel(const int* __restrict__ pos) {
    int i = blockIdx.x * 256 + threadIdx.x;
    int p = pos[i];
    int f = i >> 11;
    if (p > 0) atomicAdd(&d_cntp[f], 1);
    else if (p < 0) atomicAdd(&d_cntn[f], 1);
}

// warp-per-column GEMV: biasbig[3072+n] = b1[n] + sum_k x[k]*W1[k][n]
__global__ void prep_kernel(const float* __restrict__ x,
                            const float* __restrict__ Wa1, const float* __restrict__ ba1,
                            const float* __restrict__ Wg1, const float* __restrict__ bg1) {
    int n = (blockIdx.x << 4) + (threadIdx.x >> 5);  // grid 16 x 512 -> n 0..255
    int lane = threadIdx.x & 31;
    const float* W = (n < 128) ? Wa1 : Wg1;
    int col = n & 127;
    float s = 0.0f;
    for (int k = lane; k < D_IN; k += 32) s += x[k] * W[k * 128 + col];
#pragma unroll
    for (int off = 16; off; off >>= 1) s += __shfl_xor_sync(0xffffffffu, s, off);
    if (lane == 0) d_biasbig[G3H + n] = s + ((n < 128) ? ba1[col] : bg1[col]);
}

// ---------------- elementwise / reduction kernels ----------------
__global__ void tension_kernel() {
    int row  = blockIdx.x * 8 + (threadIdx.x >> 5);
    int lane = threadIdx.x & 31;
    const __half2* o = reinterpret_cast<const __half2*>(d_soutput_h + (size_t)row * 512);
    float s = 0.0f;
    for (int c = lane; c < 256; c += 32) {
        float2 v = __half22float2(o[c]);
        s += v.x * v.x + v.y * v.y;
    }
#pragma unroll
    for (int off = 16; off; off >>= 1) s += __shfl_xor_sync(0xffffffffu, s, off);
    __shared__ float wsum[8];
    __shared__ float wmax[8];
    float t = s * (1.0f / 512.0f);
    if (lane == 0) {
        d_tension[row] = t;
        wsum[threadIdx.x >> 5] = t;
        wmax[threadIdx.x >> 5] = t;
    }
    __syncthreads();
    if (threadIdx.x == 0) {
        float a = 0.0f, m = 0.0f;
        for (int w = 0; w < 8; w++) { a += wsum[w]; m = fmaxf(m, wmax[w]); }
        atomicAdd(&d_tsum, a);
        atomicMax(&d_tmax_i, __float_as_int(m));   // tension >= 0, int cmp ok
    }
}

__global__ void sumexp_kernel() {
    int i = blockIdx.x * 256 + threadIdx.x;
    float tmax = __int_as_float(d_tmax_i);
    float e = __expf(d_tension[i] - tmax);
    d_ebuf[i] = e;
    __shared__ float sh[256];
    sh[threadIdx.x] = e;
    __syncthreads();
    for (int s = 128; s; s >>= 1) {
        if (threadIdx.x < s) sh[threadIdx.x] += sh[threadIdx.x + s];
        __syncthreads();
    }
    if (threadIdx.x == 0) atomicAdd(&d_sumexp, sh[0]);
}

// GRU combine + wealth mod + clip; half2 vectorized (2 elems/thread)
__global__ void gru_kernel(const float* __restrict__ hid, const float* __restrict__ wealth) {
    size_t t = (size_t)blockIdx.x * 256 + threadIdx.x;   // 0 .. 8.39M
    int i  = (int)(t >> 9);          // row
    int j2 = (int)(t & 511);         // half2 index within 1024-wide row
    const __half2* gi = reinterpret_cast<const __half2*>(d_gi_h + (size_t)i * G3H);
    const __half2* gh = reinterpret_cast<const __half2*>(d_gh_h + (size_t)i * G3H);
    float2 gir = __half22float2(gi[j2]);
    float2 giz = __half22float2(gi[j2 + 512]);
    float2 gin = __half22float2(gi[j2 + 1024]);
    float2 ghr = __half22float2(gh[j2]);
    float2 ghz = __half22float2(gh[j2 + 512]);
    float2 ghn = __half22float2(gh[j2 + 1024]);
    float2 h = *reinterpret_cast<const float2*>(hid + (size_t)i * 1024 + j2 * 2);
    float w = wealth[i];
    float mod = 0.9f + 0.1f * fminf(fmaxf(w, 0.1f), 2.0f);

    float r0 = fast_sigmoid(gir.x + ghr.x);
    float z0 = fast_sigmoid(giz.x + ghz.x);
    float n0 = fast_tanh(gin.x + r0 * ghn.x);
    float nh0 = fminf(fmaxf(((1.0f - z0) * n0 + z0 * h.x) * mod, -10.0f), 10.0f);

    float r1 = fast_sigmoid(gir.y + ghr.y);
    float z1 = fast_sigmoid(giz.y + ghz.y);
    float n1 = fast_tanh(gin.y + r1 * ghn.y);
    float nh1 = fminf(fmaxf(((1.0f - z1) * n1 + z1 * h.y) * mod, -10.0f), 10.0f);

    *reinterpret_cast<float2*>(d_hpost + (size_t)i * 1024 + j2 * 2) = make_float2(nh0, nh1);
}

// per-faction column sums, row-chunked: grid (8, 8, 8)
__global__ void stats_kernel(const int* __restrict__ pos) {
    int f = blockIdx.x;                          // faction
    int j = blockIdx.y * 128 + threadIdx.x;      // column
    int r0 = blockIdx.z * 256;                   // row chunk within faction
    int base = f * FS + r0;
    float sa = 0.0f, sp = 0.0f, sn = 0.0f;
    for (int r = 0; r < 256; r++) {
        float v = d_hpost[(size_t)(base + r) * D_HID + j];
        int p = pos[base + r];
        sa += v;
        if (p > 0) sp += v; else if (p < 0) sn += v;
    }
    atomicAdd(&d_sumall[f * D_HID + j], sa);
    atomicAdd(&d_sumpos[f * D_HID + j], sp);
    atomicAdd(&d_sumneg[f * D_HID + j], sn);
}

__global__ void statsfinal_kernel() {
    int j = threadIdx.x;           // 0..1023
    int cp = 0, cn = 0;
    for (int f = 0; f < NF; f++) { cp += d_cntp[f]; cn += d_cntn[f]; }
    float sp = 0.0f, sn = 0.0f;
    for (int f = 0; f < NF; f++) { sp += d_sumpos[f * D_HID + j]; sn += d_sumneg[f * D_HID + j]; }
    float mp = sp / (float)max(cp, 1);
    float mn = sn / (float)max(cn, 1);
    d_meanp[j] = mp; d_meann[j] = mn;
    float g = 0.0f;
    for (int f = 0; f < NF; f++) {
        float adj = d_sumall[f * D_HID + j];
        if (cp >= 2) adj += 0.1f * ((float)d_cntp[f] * mp - d_sumpos[f * D_HID + j]);
        if (cn >= 2) adj += 0.1f * ((float)d_cntn[f] * mn - d_sumneg[f * D_HID + j]);
        float F = adj * (1.0f / (float)FS);
        d_F[f * D_HID + j] = F;
        g += F;
    }
    d_gop[j] = g * (1.0f / (float)NF);
    if (j == 0) { d_cnt_tot[0] = cp; d_cnt_tot[1] = cn; }
}

// apply syncs + debate; float4 per thread
__global__ void final_kernel(const int* __restrict__ pos, const int* __restrict__ step,
                             float* __restrict__ out) {
    size_t t = (size_t)blockIdx.x * 256 + threadIdx.x;   // 0 .. 4.19M
    int i = (int)(t >> 8);
    int j = (int)(t & 255) * 4;
    float4 h4 = *reinterpret_cast<const float4*>(d_hpost + (size_t)i * 1024 + j);
    int p = pos[i];
    int cp = d_cnt_tot[0], cn = d_cnt_tot[1];
    float* hv = (float*)&h4;
    if (p > 0 && cp >= 2) {
        const float4 m4 = *reinterpret_cast<const float4*>(d_meanp + j);
        const float* mv = (const float*)&m4;
#pragma unroll
        for (int q = 0; q < 4; q++) hv[q] = 0.9f * hv[q] + 0.1f * mv[q];
    } else if (p < 0 && cn >= 2) {
        const float4 m4 = *reinterpret_cast<const float4*>(d_meann + j);
        const float* mv = (const float*)&m4;
#pragma unroll
        for (int q = 0; q < 4; q++) hv[q] = 0.9f * hv[q] + 0.1f * mv[q];
    }
    int f = i >> 11;
    const float4 F4 = *reinterpret_cast<const float4*>(d_F + f * D_HID + j);
    const float* Fv = (const float*)&F4;
#pragma unroll
    for (int q = 0; q < 4; q++) hv[q] = 0.85f * hv[q] + 0.15f * Fv[q];
    if (*step > 5 && (i & (FS - 1)) < (FS / 4)) {
        const float4 g4 = *reinterpret_cast<const float4*>(d_gop + j);
        const float* gv = (const float*)&g4;
#pragma unroll
        for (int q = 0; q < 4; q++) hv[q] = 0.85f * hv[q] + 0.15f * gv[q];
    }
    float* o = out + 513 + (size_t)i * 1024 + j;
#pragma unroll
    for (int q = 0; q < 4; q++) o[q] = hv[q];
}

// combined_out = sum_i softmax(tension)_i * output[i,:]; 256 blocks x 64 rows
__global__ void wsum_kernel() {
    int r0 = blockIdx.x * 64;
    float inv = 1.0f / d_sumexp;
    int t = threadIdx.x;
    float c0 = 0.0f, c1 = 0.0f;
    for (int r = r0; r < r0 + 64; r++) {
        float w = d_ebuf[r] * inv;
        const __half* o = d_soutput_h + (size_t)r * 512;
        c0 += w * __half2float(o[t]);
        c1 += w * __half2float(o[t + 256]);
    }
    atomicAdd(&d_cout[t], c0);
    atomicAdd(&d_cout[t + 256], c1);
}

// split-K GEMV: out[t] += sum_{k in chunk} cout[k]*Wo[k][t]; bias seeded in init
__global__ void pred_kernel(const float* __restrict__ Wo, float* __restrict__ out) {
    __shared__ float co[64];
    int b = blockIdx.x;      // 0..7
    int t = threadIdx.x;     // 0..511
    if (t < 64) co[t] = d_cout[b * 64 + t];
    __syncthreads();
    float s = 0.0f;
#pragma unroll 8
    for (int k = 0; k < 64; k++) s += co[k] * Wo[(size_t)(b * 64 + k) * 512 + t];
    atomicAdd(&out[t], s);
    if (b == 0 && t == 0) out[512] = d_tsum * (1.0f / (float)N_CELLS);
}

// ---------------- launch ----------------
extern "C" void kernel_launch(void* const* d_in, const int* in_sizes, int n_in,
                              void* d_out, int out_size) {
    const float* x        = (const float*)d_in[0];
    const float* hiddens  = (const float*)d_in[1];
    const float* wealth   = (const float*)d_in[2];
    const float* Wa1      = (const float*)d_in[3];
    const float* ba1      = (const float*)d_in[4];
    const float* Wa2      = (const float*)d_in[5];
    const float* ba2      = (const float*)d_in[6];
    const float* Wg1      = (const float*)d_in[7];
    const float* bg1      = (const float*)d_in[8];
    const float* Wg2      = (const float*)d_in[9];
    const float* bg2      = (const float*)d_in[10];
    const float* W_ih     = (const float*)d_in[11];
    const float* W_hh     = (const float*)d_in[12];
    const float* b_ih     = (const float*)d_in[13];
    const float* b_hh     = (const float*)d_in[14];
    const float* Wo       = (const float*)d_in[15];
    const float* bo       = (const float*)d_in[16];
    const int*   positions= (const int*)d_in[17];
    const int*   step     = (const int*)d_in[18];
    float* out = (float*)d_out;

    void *p_srelu_h, *p_soutput_h, *p_w2t, *p_w2h, *p_bias2, *p_wbig, *p_biasbig;
    void *p_hid_h, *p_wih_t, *p_w2wt, *p_beff, *p_gi_h, *p_gh_h, *p_tension;
    cudaGetSymbolAddress(&p_srelu_h,   d_srelu_h);
    cudaGetSymbolAddress(&p_soutput_h, d_soutput_h);
    cudaGetSymbolAddress(&p_w2t,       d_w2t);
    cudaGetSymbolAddress(&p_w2h,       d_w2h);
    cudaGetSymbolAddress(&p_bias2,     d_bias2);
    cudaGetSymbolAddress(&p_wbig,      d_wbig);
    cudaGetSymbolAddress(&p_biasbig,   d_biasbig);
    cudaGetSymbolAddress(&p_hid_h,     d_hid_h);
    cudaGetSymbolAddress(&p_wih_t,     d_wih_t);
    cudaGetSymbolAddress(&p_w2wt,      d_w2wt);
    cudaGetSymbolAddress(&p_beff,      d_beff);
    cudaGetSymbolAddress(&p_gi_h,      d_gi_h);
    cudaGetSymbolAddress(&p_gh_h,      d_gh_h);
    cudaGetSymbolAddress(&p_tension,   d_tension);

    const int SMEM_BYTES = 3 * STAGE_H * 2;   // 61440
    cudaFuncSetAttribute(gemm_fp16,
                         cudaFuncAttributeMaxDynamicSharedMemorySize, SMEM_BYTES);

    init_kernel<<<64, 512>>>(bo, b_hh, out);                                 // 1
    transpose_half<<<dim3(96, 32), dim3(32, 8)>>>(W_hh, (__half*)p_wbig, 1024, 3072); // 2
    cvt_half<<<16384, 256>>>(hiddens, (__half*)p_hid_h);                     // 3
    w1t_kernel<<<dim3(4, 256), 256>>>(Wa1, Wg1);                             // 4
    prep_kernel<<<16, 512>>>(x, Wa1, ba1, Wg1, bg1);                         // 5

    // fused: [gh | H1] = hid @ [W_hh | W1] + [b_hh | xvec]  [112 GF]
    gemm_fp16<<<dim3(26, 128), 256, SMEM_BYTES>>>(                           // 6
        (const __half*)p_hid_h, 1024, (const __half*)p_wbig,
        nullptr, nullptr, 0, 1024, 4,
        (const float*)p_biasbig, nullptr, nullptr);

    transpose_half<<<dim3(96, 16), dim3(32, 8)>>>(W_ih, (__half*)p_wih_t, 512, 3072);  // 7
    w2t_kernel<<<dim3(1, 512), 256>>>(Wa2, ba2, Wg2, bg2);                   // 8

    // W2W^T [3072 x 256] = wih_t @ w2h^T  (W2W^T[m][n] = (W2cat@W_ih)[n][m])
    gemm_fp16<<<dim3(2, 24), 256, SMEM_BYTES>>>(                             // 9
        (const __half*)p_wih_t, 512, (const __half*)p_w2h,
        nullptr, (__half*)p_w2wt, 256, 512, 8 | 16 | 32,
        (const float*)p_bias2, nullptr, nullptr);

    beff_kernel<<<384, 256>>>(b_ih);                                         // 10
    count_kernel<<<64, 256>>>(positions);                                    // 11

    // soutput = H1 @ [Wa2;-Wg2] + bias2 -> fp16 only
    gemm_fp16<<<dim3(4, 128), 256, SMEM_BYTES>>>(                            // 12
        (const __half*)p_srelu_h, 256, (const __half*)p_w2t,
        nullptr, (__half*)p_soutput_h, 512, 256, 8 | 16,
        (const float*)p_bias2, nullptr, nullptr);

    tension_kernel<<<2048, 256>>>();                                         // 13
    sumexp_kernel<<<64, 256>>>();                                            // 14

    // gi = H1 @ W2W + beff + tension x W_ih[512]  [25.8 GF, K=256] -> fp16
    gemm_fp16<<<dim3(24, 128), 256, SMEM_BYTES>>>(                           // 15
        (const __half*)p_srelu_h, 256, (const __half*)p_w2wt,
        nullptr, (__half*)p_gi_h, 3072, 256, 2 | 8 | 16,
        (const float*)p_beff, (const float*)p_tension,
        W_ih + (size_t)512 * 3072);

    gru_kernel<<<32768, 256>>>(hiddens, wealth);                             // 16
    stats_kernel<<<dim3(8, 8, 8), 128>>>(positions);                         // 17
    statsfinal_kernel<<<1, 1024>>>();                                        // 18
    final_kernel<<<16384, 256>>>(positions, step, out);                      // 19
    wsum_kernel<<<256, 256>>>();                                             // 20
    pred_kernel<<<8, 512>>>(Wo, out);                                        // 21
}

// round 14
// speedup vs baseline: 1.5458x; 1.3041x over previous
#include <cuda_runtime.h>
#include <cuda_fp16.h>
#include <mma.h>
#include <math.h>
#include <stdint.h>

using namespace nvcuda;

#define N_CELLS 16384
#define D_IN    512
#define D_HID   1024
#define D_OUT   512
#define G3H     3072
#define NF      8
#define FS      2048
#define NBIG    3328   // 3072 (gh) + 256 (H1)
#define NGI     3584   // 512 (soutput) + 3072 (gi)

// ---------------- device scratch (static, allocation-free) ----------------
__device__ __half d_wbig[(size_t)NBIG * D_HID];        // [W_hh^T ; W1^T] K-major
__device__ float  d_biasbig[NBIG];                     // [b_hh | xvec]
__device__ __half d_wgi[(size_t)NGI * 256];            // [[Wa2;-Wg2]^T ; W2W^T] K-major
__device__ float  d_bcat[NGI];                         // [bias2 | beff]
__device__ __half d_w2h[256 * 512];                    // [M=256][K=512] W2cat row-major
__device__ float  d_bias2[512];                        // ba2 - bg2
__device__ __half d_wih_t[(size_t)G3H * D_OUT];        // W_ih[:512]^T [3072][512]
__device__ __half d_hid_h[(size_t)N_CELLS * D_HID];    // fp16 hiddens
__device__ __half d_srelu_h[(size_t)N_CELLS * 256];    // fp16 relu acts (a|g)
__device__ __half d_soutput_h[(size_t)N_CELLS * 512];  // fp16 output = a - g
__device__ float  d_tension[N_CELLS];
__device__ float  d_ebuf[N_CELLS];
__device__ __half d_gi_h[(size_t)N_CELLS * G3H];       // fp16 gi preacts (no t-term)
__device__ __half d_gh_h[(size_t)N_CELLS * G3H];       // fp16 gh preacts
__device__ float  d_hpost[(size_t)N_CELLS * D_HID];
__device__ float  d_sumall[NF * D_HID];
__device__ float  d_sumpos[NF * D_HID];
__device__ float  d_sumneg[NF * D_HID];
__device__ float  d_meanp[D_HID];
__device__ float  d_meann[D_HID];
__device__ float  d_F[NF * D_HID];
__device__ float  d_gop[D_HID];
__device__ int    d_cntp[NF];
__device__ int    d_cntn[NF];
__device__ int    d_cnt_tot[2];
__device__ float  d_tsum;
__device__ float  d_sumexp;
__device__ int    d_tmax_i;
__device__ float  d_cout[512];

// ---------------- cp.async helpers ----------------
__device__ __forceinline__ void cp16(uint32_t daddr, const void* src) {
    asm volatile("cp.async.cg.shared.global [%0], [%1], 16;" :: "r"(daddr), "l"(src));
}
__device__ __forceinline__ void cp_commit() {
    asm volatile("cp.async.commit_group;" ::: "memory");
}
template <int N>
__device__ __forceinline__ void cp_wait() {
    asm volatile("cp.async.wait_group %0;" :: "n"(N) : "memory");
}

__device__ __forceinline__ float fast_sigmoid(float x) {
    return 1.0f / (1.0f + __expf(-x));
}
__device__ __forceinline__ float fast_tanh(float x) {
    float a = fabsf(x);
    float e = __expf(-2.0f * a);
    float r = (1.0f - e) / (1.0f + e);
    return copysignf(r, x);
}

// ---------------- pipelined fp16 WMMA GEMM (proven config) ----------------
// C[M x Ntot] = A[M x K] (fp16, row-major) * Bt[Ntot x K] (fp16, K-major)^T
// Block tile 128x128, BK=32, 3-stage cp.async pipeline, 256 threads,
// warp grid 2x4 (warp tile 64x32), fp32 accumulate, 2 CTAs/SM.
// modes: 1=relu, 8=write half Ch, 16=skip fp32 C, 32=no bias,
//        4=fused gh+H1 epilogue, 64=fused soutput+gi epilogue
#define STAGE_H 10240   // halves per stage: A 128x40 + B 128x40

__global__ void __launch_bounds__(256, 2) gemm_fp16(
    const __half* __restrict__ A, int lda,
    const __half* __restrict__ Bt,
    float* __restrict__ C, __half* __restrict__ Ch, int ldc,
    int K, int mode,
    const float* __restrict__ bias)
{
    extern __shared__ __align__(16) char smem_raw[];
    __half* smem = (__half*)smem_raw;
    const uint32_t sbase = (uint32_t)__cvta_generic_to_shared(smem);

    const int tid  = threadIdx.x;
    const int bm   = blockIdx.y * 128;
    const int bn   = blockIdx.x * 128;
    const int warp = tid >> 5;
    const int wr   = warp & 1;   // 2 warp rows of 64
    const int wc   = warp >> 1;  // 4 warp cols of 32

    wmma::fragment<wmma::accumulator, 16, 16, 16, float> acc[4][2];
#pragma unroll
    for (int i = 0; i < 4; i++)
#pragma unroll
        for (int j = 0; j < 2; j++) wmma::fill_fragment(acc[i][j], 0.0f);

    const int crow = tid >> 1;           // 0..127
    const int ccol = (tid & 1) << 4;     // 0 or 16 (halves)

#define ISSUE(KT)                                                              \
    {                                                                          \
        uint32_t so = ((KT) % 3) * STAGE_H;                                    \
        int k0 = (KT) << 5;                                                    \
        _Pragma("unroll")                                                      \
        for (int h2 = 0; h2 < 2; h2++) {                                       \
            int cc = ccol + h2 * 8;                                            \
            cp16(sbase + (so + crow * 40 + cc) * 2,                            \
                 A + (size_t)(bm + crow) * lda + k0 + cc);                     \
            cp16(sbase + (so + 5120 + crow * 40 + cc) * 2,                     \
                 Bt + (size_t)(bn + crow) * K + k0 + cc);                      \
        }                                                                      \
        cp_commit();                                                           \
    }

#define MMA_TILE(KT)                                                           \
    {                                                                          \
        __half* As = smem + ((KT) % 3) * STAGE_H;                              \
        __half* Bs = As + 5120;                                                \
        _Pragma("unroll")                                                      \
        for (int kk = 0; kk < 32; kk += 16) {                                  \
            wmma::fragment<wmma::matrix_a, 16, 16, 16, __half, wmma::row_major> af[4]; \
            wmma::fragment<wmma::matrix_b, 16, 16, 16, __half, wmma::col_major> bf[2]; \
            _Pragma("unroll")                                                  \
            for (int i = 0; i < 4; i++)                                        \
                wmma::load_matrix_sync(af[i], As + (wr * 64 + i * 16) * 40 + kk, 40); \
            _Pragma("unroll")                                                  \
            for (int j = 0; j < 2; j++)                                        \
                wmma::load_matrix_sync(bf[j], Bs + (wc * 32 + j * 16) * 40 + kk, 40); \
            _Pragma("unroll")                                                  \
            for (int i = 0; i < 4; i++)                                        \
                _Pragma("unroll")                                              \
                for (int j = 0; j < 2; j++)                                    \
                    wmma::mma_sync(acc[i][j], af[i], bf[j], acc[i][j]);        \
        }                                                                      \
    }

    const int nk = K >> 5;
    ISSUE(0)
    ISSUE(1)

    for (int kt = 0; kt < nk - 1; kt++) {
        cp_wait<1>();
        __syncthreads();
        if (kt + 2 < nk) ISSUE(kt + 2)
        MMA_TILE(kt)
    }
    cp_wait<0>();
    __syncthreads();
    MMA_TILE(nk - 1)
#undef ISSUE
#undef MMA_TILE

    // epilogue in two 64-col halves staged through shared (floats, stride 72)
    float* Cs = (float*)smem;
#pragma unroll
    for (int h = 0; h < 2; h++) {
        __syncthreads();
        if ((wc >> 1) == h) {
            const int lc = (wc & 1) << 5;
#pragma unroll
            for (int i = 0; i < 4; i++)
#pragma unroll
                for (int j = 0; j < 2; j++)
                    wmma::store_matrix_sync(Cs + (wr * 64 + i * 16) * 72 + lc + j * 16,
                                            acc[i][j], 72, wmma::mem_row_major);
        }
        __syncthreads();
#pragma unroll
        for (int it = 0; it < 32; it++) {
            int idx = it * 256 + tid;
            int r = idx >> 6, c = idx & 63;
            int gr = bm + r, gc = bn + (h << 6) + c;
            float v = Cs[r * 72 + c];
            if (!(mode & 32)) v += bias[gc];
            if (mode & 4) {
                // fused gh + H1 epilogue
                if (gc < G3H) d_gh_h[(size_t)gr * G3H + gc] = __float2half(v);
                else d_srelu_h[(size_t)gr * 256 + (gc - G3H)] =
                         __float2half(fmaxf(v, 0.0f));
            } else if (mode & 64) {
                // fused soutput + gi epilogue
                if (gc < 512) d_soutput_h[(size_t)gr * 512 + gc] = __float2half(v);
                else d_gi_h[(size_t)gr * G3H + (gc - 512)] = __float2half(v);
            } else {
                if (mode & 1) v = fmaxf(v, 0.0f);
                if (!(mode & 16)) C[(size_t)gr * ldc + gc] = v;
                if (mode & 8)  Ch[(size_t)gr * ldc + gc] = __float2half(v);
            }
        }
    }
}

// ---------------- prep kernels ----------------
__global__ void cvt_half(const float* __restrict__ src, __half* __restrict__ dst) {
    size_t i = (size_t)blockIdx.x * 256 + threadIdx.x;
    float4 v = reinterpret_cast<const float4*>(src)[i];
    __half2* d = reinterpret_cast<__half2*>(dst) + i * 2;
    d[0] = __floats2half2_rn(v.x, v.y);
    d[1] = __floats2half2_rn(v.z, v.w);
}

// dst[c][r] = (half)src[r][c]; src R x Ccols, dst stride R
__global__ void transpose_half(const float* __restrict__ src, __half* __restrict__ dst,
                               int R, int Ccols) {
    __shared__ float tile[32][33];
    int c0 = blockIdx.x * 32, r0 = blockIdx.y * 32;
    int x = threadIdx.x, y = threadIdx.y;   // (32, 8)
#pragma unroll
    for (int i = 0; i < 32; i += 8)
        tile[y + i][x] = src[(size_t)(r0 + y + i) * Ccols + c0 + x];
    __syncthreads();
#pragma unroll
    for (int i = 0; i < 32; i += 8)
        dst[(size_t)(c0 + y + i) * R + r0 + x] = __float2half(tile[x][y + i]);
}

// W1^T into wbig rows 3072..3327 (K-major, stride 1024)
__global__ void w1t_kernel(const float* __restrict__ Wa1, const float* __restrict__ Wg1) {
    int n = blockIdx.y;                         // 0..255
    int k = blockIdx.x * 256 + threadIdx.x;     // 0..1023
    float v = (n < 128) ? Wa1[(size_t)(512 + k) * 128 + n]
                        : Wg1[(size_t)(512 + k) * 128 + (n - 128)];
    d_wbig[(size_t)(G3H + n) * 1024 + k] = __float2half(v);
}

// w2t (into wgi rows 0..511), w2h, bias2, bcat[0..511]
__global__ void w2t_kernel(const float* __restrict__ Wa2, const float* __restrict__ ba2,
                           const float* __restrict__ Wg2, const float* __restrict__ bg2) {
    int n = blockIdx.y;                // 0..511
    int k = threadIdx.x;               // 0..255
    float v = (k < 128) ? Wa2[(size_t)k * 512 + n] : -Wg2[(size_t)(k - 128) * 512 + n];
    d_wgi[(size_t)n * 256 + k] = __float2half(v);
    d_w2h[(size_t)k * 512 + n] = __float2half(v);
    if (k == 0) { float b = ba2[n] - bg2[n]; d_bias2[n] = b; d_bcat[n] = b; }
}

// bcat[512+c] = b_ih[c] + sum_o bias2[o] * W_ih[o][c]   (warp per c)
__global__ void beff_kernel(const float* __restrict__ b_ih) {
    int c = (blockIdx.x << 3) + (threadIdx.x >> 5);   // grid 384 x 256 -> c 0..3071
    int lane = threadIdx.x & 31;
    const __half* w = d_wih_t + (size_t)c * 512;
    float s = 0.0f;
    for (int o = lane; o < 512; o += 32) s += d_bias2[o] * __half2float(w[o]);
#pragma unroll
    for (int off = 16; off; off >>= 1) s += __shfl_xor_sync(0xffffffffu, s, off);
    if (lane == 0) d_bcat[512 + c] = s + b_ih[c];
}

// init: zero accumulators, seed out with bo, copy b_hh into biasbig
__global__ void init_kernel(const float* __restrict__ bo, const float* __restrict__ b_hh,
                            float* __restrict__ out) {
    int gid = blockIdx.x * 512 + threadIdx.x;   // grid 64 x 512 = 32768
    if (gid < NF * D_HID) {
        d_sumall[gid] = 0.0f; d_sumpos[gid] = 0.0f; d_sumneg[gid] = 0.0f;
    }
    if (gid < G3H) d_biasbig[gid] = b_hh[gid];
    if (gid < 512) { d_cout[gid] = 0.0f; out[gid] = bo[gid]; }
    if (gid >= 512 && gid < 512 + NF) { d_cntp[gid - 512] = 0; d_cntn[gid - 512] = 0; }
    if (gid == 0) { d_tsum = 0.0f; d_sumexp = 0.0f; d_tmax_i = 0; }
}

__global__ void count_kernel(const int* __restrict__ pos) {
    int i = blockIdx.x * 256 + threadIdx.x;
    int p = pos[i];
    int f = i >> 11;
    if (p > 0) atomicAdd(&d_cntp[f], 1);
    else if (p < 0) atomicAdd(&d_cntn[f], 1);
}

// warp-per-column GEMV: biasbig[3072+n] = b1[n] + sum_k x[k]*W1[k][n]
__global__ void prep_kernel(const float* __restrict__ x,
                            const float* __restrict__ Wa1, const float* __restrict__ ba1,
                            const float* __restrict__ Wg1, const float* __restrict__ bg1) {
    int n = (blockIdx.x << 4) + (threadIdx.x >> 5);  // grid 16 x 512 -> n 0..255
    int lane = threadIdx.x & 31;
    const float* W = (n < 128) ? Wa1 : Wg1;
    int col = n & 127;
    float s = 0.0f;
    for (int k = lane; k < D_IN; k += 32) s += x[k] * W[k * 128 + col];
#pragma unroll
    for (int off = 16; off; off >>= 1) s += __shfl_xor_sync(0xffffffffu, s, off);
    if (lane == 0) d_biasbig[G3H + n] = s + ((n < 128) ? ba1[col] : bg1[col]);
}

// ---------------- elementwise / reduction kernels ----------------
__global__ void tension_kernel() {
    int row  = blockIdx.x * 8 + (threadIdx.x >> 5);
    int lane = threadIdx.x & 31;
    const __half2* o = reinterpret_cast<const __half2*>(d_soutput_h + (size_t)row * 512);
    float s = 0.0f;
    for (int c = lane; c < 256; c += 32) {
        float2 v = __half22float2(o[c]);
        s += v.x * v.x + v.y * v.y;
    }
#pragma unroll
    for (int off = 16; off; off >>= 1) s += __shfl_xor_sync(0xffffffffu, s, off);
    __shared__ float wsum[8];
    __shared__ float wmax[8];
    float t = s * (1.0f / 512.0f);
    if (lane == 0) {
        d_tension[row] = t;
        wsum[threadIdx.x >> 5] = t;
        wmax[threadIdx.x >> 5] = t;
    }
    __syncthreads();
    if (threadIdx.x == 0) {
        float a = 0.0f, m = 0.0f;
        for (int w = 0; w < 8; w++) { a += wsum[w]; m = fmaxf(m, wmax[w]); }
        atomicAdd(&d_tsum, a);
        atomicMax(&d_tmax_i, __float_as_int(m));   // tension >= 0, int cmp ok
    }
}

__global__ void sumexp_kernel() {
    int i = blockIdx.x * 256 + threadIdx.x;
    float tmax = __int_as_float(d_tmax_i);
    float e = __expf(d_tension[i] - tmax);
    d_ebuf[i] = e;
    __shared__ float sh[256];
    sh[threadIdx.x] = e;
    __syncthreads();
    for (int s = 128; s; s >>= 1) {
        if (threadIdx.x < s) sh[threadIdx.x] += sh[threadIdx.x + s];
        __syncthreads();
    }
    if (threadIdx.x == 0) atomicAdd(&d_sumexp, sh[0]);
}

// GRU combine + wealth mod + clip; half2 vectorized; adds tension rank-1 term
__global__ void gru_kernel(const float* __restrict__ hid, const float* __restrict__ wealth,
                           const float* __restrict__ wih512) {
    size_t t = (size_t)blockIdx.x * 256 + threadIdx.x;   // 0 .. 8.39M
    int i  = (int)(t >> 9);          // row
    int j2 = (int)(t & 511);         // half2 index within 1024-wide row
    const __half2* gi = reinterpret_cast<const __half2*>(d_gi_h + (size_t)i * G3H);
    const __half2* gh = reinterpret_cast<const __half2*>(d_gh_h + (size_t)i * G3H);
    float2 gir = __half22float2(gi[j2]);
    float2 giz = __half22float2(gi[j2 + 512]);
    float2 gin = __half22float2(gi[j2 + 1024]);
    float2 ghr = __half22float2(gh[j2]);
    float2 ghz = __half22float2(gh[j2 + 512]);
    float2 ghn = __half22float2(gh[j2 + 1024]);
    float2 h = *reinterpret_cast<const float2*>(hid + (size_t)i * 1024 + j2 * 2);
    float tn = d_tension[i];
    float2 wr = *reinterpret_cast<const float2*>(wih512 + j2 * 2);
    float2 wz = *reinterpret_cast<const float2*>(wih512 + 1024 + j2 * 2);
    float2 wn = *reinterpret_cast<const float2*>(wih512 + 2048 + j2 * 2);
    float w = wealth[i];
    float mod = 0.9f + 0.1f * fminf(fmaxf(w, 0.1f), 2.0f);

    float r0 = fast_sigmoid(gir.x + ghr.x + tn * wr.x);
    float z0 = fast_sigmoid(giz.x + ghz.x + tn * wz.x);
    float n0 = fast_tanh(gin.x + tn * wn.x + r0 * ghn.x);
    float nh0 = fminf(fmaxf(((1.0f - z0) * n0 + z0 * h.x) * mod, -10.0f), 10.0f);

    float r1 = fast_sigmoid(gir.y + ghr.y + tn * wr.y);
    float z1 = fast_sigmoid(giz.y + ghz.y + tn * wz.y);
    float n1 = fast_tanh(gin.y + tn * wn.y + r1 * ghn.y);
    float nh1 = fminf(fmaxf(((1.0f - z1) * n1 + z1 * h.y) * mod, -10.0f), 10.0f);

    *reinterpret_cast<float2*>(d_hpost + (size_t)i * 1024 + j2 * 2) = make_float2(nh0, nh1);
}

// per-faction column sums, row-chunked: grid (8, 8, 8)
__global__ void stats_kernel(const int* __restrict__ pos) {
    int f = blockIdx.x;                          // faction
    int j = blockIdx.y * 128 + threadIdx.x;      // column
    int r0 = blockIdx.z * 256;                   // row chunk within faction
    int base = f * FS + r0;
    float sa = 0.0f, sp = 0.0f, sn = 0.0f;
    for (int r = 0; r < 256; r++) {
        float v = d_hpost[(size_t)(base + r) * D_HID + j];
        int p = pos[base + r];
        sa += v;
        if (p > 0) sp += v; else if (p < 0) sn += v;
    }
    atomicAdd(&d_sumall[f * D_HID + j], sa);
    atomicAdd(&d_sumpos[f * D_HID + j], sp);
    atomicAdd(&d_sumneg[f * D_HID + j], sn);
}

__global__ void statsfinal_kernel() {
    int j = threadIdx.x;           // 0..1023
    int cp = 0, cn = 0;
    for (int f = 0; f < NF; f++) { cp += d_cntp[f]; cn += d_cntn[f]; }
    float sp = 0.0f, sn = 0.0f;
    for (int f = 0; f < NF; f++) { sp += d_sumpos[f * D_HID + j]; sn += d_sumneg[f * D_HID + j]; }
    float mp = sp / (float)max(cp, 1);
    float mn = sn / (float)max(cn, 1);
    d_meanp[j] = mp; d_meann[j] = mn;
    float g = 0.0f;
    for (int f = 0; f < NF; f++) {
        float adj = d_sumall[f * D_HID + j];
        if (cp >= 2) adj += 0.1f * ((float)d_cntp[f] * mp - d_sumpos[f * D_HID + j]);
        if (cn >= 2) adj += 0.1f * ((float)d_cntn[f] * mn - d_sumneg[f * D_HID + j]);
        float F = adj * (1.0f / (float)FS);
        d_F[f * D_HID + j] = F;
        g += F;
    }
    d_gop[j] = g * (1.0f / (float)NF);
    if (j == 0) { d_cnt_tot[0] = cp; d_cnt_tot[1] = cn; }
}

// apply syncs + debate; float4 per thread
__global__ void final_kernel(const int* __restrict__ pos, const int* __restrict__ step,
                             float* __restrict__ out) {
    size_t t = (size_t)blockIdx.x * 256 + threadIdx.x;   // 0 .. 4.19M
    int i = (int)(t >> 8);
    int j = (int)(t & 255) * 4;
    float4 h4 = *reinterpret_cast<const float4*>(d_hpost + (size_t)i * 1024 + j);
    int p = pos[i];
    int cp = d_cnt_tot[0], cn = d_cnt_tot[1];
    float* hv = (float*)&h4;
    if (p > 0 && cp >= 2) {
        const float4 m4 = *reinterpret_cast<const float4*>(d_meanp + j);
        const float* mv = (const float*)&m4;
#pragma unroll
        for (int q = 0; q < 4; q++) hv[q] = 0.9f * hv[q] + 0.1f * mv[q];
    } else if (p < 0 && cn >= 2) {
        const float4 m4 = *reinterpret_cast<const float4*>(d_meann + j);
        const float* mv = (const float*)&m4;
#pragma unroll
        for (int q = 0; q < 4; q++) hv[q] = 0.9f * hv[q] + 0.1f * mv[q];
    }
    int f = i >> 11;
    const float4 F4 = *reinterpret_cast<const float4*>(d_F + f * D_HID + j);
    const float* Fv = (const float*)&F4;
#pragma unroll
    for (int q = 0; q < 4; q++) hv[q] = 0.85f * hv[q] + 0.15f * Fv[q];
    if (*step > 5 && (i & (FS - 1)) < (FS / 4)) {
        const float4 g4 = *reinterpret_cast<const float4*>(d_gop + j);
        const float* gv = (const float*)&g4;
#pragma unroll
        for (int q = 0; q < 4; q++) hv[q] = 0.85f * hv[q] + 0.15f * gv[q];
    }
    float* o = out + 513 + (size_t)i * 1024 + j;
#pragma unroll
    for (int q = 0; q < 4; q++) o[q] = hv[q];
}

// combined_out = sum_i softmax(tension)_i * output[i,:]; 256 blocks x 64 rows
__global__ void wsum_kernel() {
    int r0 = blockIdx.x * 64;
    float inv = 1.0f / d_sumexp;
    int t = threadIdx.x;
    float c0 = 0.0f, c1 = 0.0f;
    for (int r = r0; r < r0 + 64; r++) {
        float w = d_ebuf[r] * inv;
        const __half* o = d_soutput_h + (size_t)r * 512;
        c0 += w * __half2float(o[t]);
        c1 += w * __half2float(o[t + 256]);
    }
    atomicAdd(&d_cout[t], c0);
    atomicAdd(&d_cout[t + 256], c1);
}

// split-K GEMV: out[t] += sum_{k in chunk} cout[k]*Wo[k][t]; bias seeded in init
__global__ void pred_kernel(const float* __restrict__ Wo, float* __restrict__ out) {
    __shared__ float co[64];
    int b = blockIdx.x;      // 0..7
    int t = threadIdx.x;     // 0..511
    if (t < 64) co[t] = d_cout[b * 64 + t];
    __syncthreads();
    float s = 0.0f;
#pragma unroll 8
    for (int k = 0; k < 64; k++) s += co[k] * Wo[(size_t)(b * 64 + k) * 512 + t];
    atomicAdd(&out[t], s);
    if (b == 0 && t == 0) out[512] = d_tsum * (1.0f / (float)N_CELLS);
}

// ---------------- launch ----------------
extern "C" void kernel_launch(void* const* d_in, const int* in_sizes, int n_in,
                              void* d_out, int out_size) {
    const float* x        = (const float*)d_in[0];
    const float* hiddens  = (const float*)d_in[1];
    const float* wealth   = (const float*)d_in[2];
    const float* Wa1      = (const float*)d_in[3];
    const float* ba1      = (const float*)d_in[4];
    const float* Wa2      = (const float*)d_in[5];
    const float* ba2      = (const float*)d_in[6];
    const float* Wg1      = (const float*)d_in[7];
    const float* bg1      = (const float*)d_in[8];
    const float* Wg2      = (const float*)d_in[9];
    const float* bg2      = (const float*)d_in[10];
    const float* W_ih     = (const float*)d_in[11];
    const float* W_hh     = (const float*)d_in[12];
    const float* b_ih     = (const float*)d_in[13];
    const float* b_hh     = (const float*)d_in[14];
    const float* Wo       = (const float*)d_in[15];
    const float* bo       = (const float*)d_in[16];
    const int*   positions= (const int*)d_in[17];
    const int*   step     = (const int*)d_in[18];
    float* out = (float*)d_out;

    void *p_srelu_h, *p_w2h, *p_wbig, *p_biasbig, *p_wgi, *p_bcat;
    void *p_hid_h, *p_wih_t;
    cudaGetSymbolAddress(&p_srelu_h,   d_srelu_h);
    cudaGetSymbolAddress(&p_w2h,       d_w2h);
    cudaGetSymbolAddress(&p_wbig,      d_wbig);
    cudaGetSymbolAddress(&p_biasbig,   d_biasbig);
    cudaGetSymbolAddress(&p_wgi,       d_wgi);
    cudaGetSymbolAddress(&p_bcat,      d_bcat);
    cudaGetSymbolAddress(&p_hid_h,     d_hid_h);
    cudaGetSymbolAddress(&p_wih_t,     d_wih_t);

    const int SMEM_BYTES = 3 * STAGE_H * 2;   // 61440
    cudaFuncSetAttribute(gemm_fp16,
                         cudaFuncAttributeMaxDynamicSharedMemorySize, SMEM_BYTES);

    init_kernel<<<64, 512>>>(bo, b_hh, out);                                 // 1
    transpose_half<<<dim3(96, 32), dim3(32, 8)>>>(W_hh, (__half*)p_wbig, 1024, 3072); // 2
    cvt_half<<<16384, 256>>>(hiddens, (__half*)p_hid_h);                     // 3
    w1t_kernel<<<dim3(4, 256), 256>>>(Wa1, Wg1);                             // 4
    prep_kernel<<<16, 512>>>(x, Wa1, ba1, Wg1, bg1);                         // 5

    // fused: [gh | H1] = hid @ [W_hh | W1] + [b_hh | xvec]  [112 GF]
    gemm_fp16<<<dim3(26, 128), 256, SMEM_BYTES>>>(                           // 6
        (const __half*)p_hid_h, 1024, (const __half*)p_wbig,
        nullptr, nullptr, 0, 1024, 4, (const float*)p_biasbig);

    transpose_half<<<dim3(96, 16), dim3(32, 8)>>>(W_ih, (__half*)p_wih_t, 512, 3072);  // 7
    w2t_kernel<<<dim3(1, 512), 256>>>(Wa2, ba2, Wg2, bg2);                   // 8

    // W2W^T [3072 x 256] = wih_t @ w2h^T -> wgi rows 512..3583
    gemm_fp16<<<dim3(2, 24), 256, SMEM_BYTES>>>(                             // 9
        (const __half*)p_wih_t, 512, (const __half*)p_w2h,
        nullptr, (__half*)p_wgi + (size_t)512 * 256, 256, 512, 8 | 16 | 32,
        nullptr);

    beff_kernel<<<384, 256>>>(b_ih);                                         // 10
    count_kernel<<<64, 256>>>(positions);                                    // 11

    // fused: [soutput | gi] = H1 @ [W2cat | W2W] + [bias2 | beff]  [30 GF, K=256]
    gemm_fp16<<<dim3(28, 128), 256, SMEM_BYTES>>>(                           // 12
        (const __half*)p_srelu_h, 256, (const __half*)p_wgi,
        nullptr, nullptr, 0, 256, 64, (const float*)p_bcat);

    tension_kernel<<<2048, 256>>>();                                         // 13
    sumexp_kernel<<<64, 256>>>();                                            // 14

    gru_kernel<<<32768, 256>>>(hiddens, wealth, W_ih + (size_t)512 * 3072);  // 15
    stats_kernel<<<dim3(8, 8, 8), 128>>>(positions);                         // 16
    statsfinal_kernel<<<1, 1024>>>();                                        // 17
    final_kernel<<<16384, 256>>>(positions, step, out);                      // 18
    wsum_kernel<<<256, 256>>>();                                             // 19
    pred_kernel<<<8, 512>>>(Wo, out);                                        // 20
}

// round 15
// speedup vs baseline: 1.5743x; 1.0184x over previous
#include <cuda_runtime.h>
#include <cuda_fp16.h>
#include <mma.h>
#include <math.h>
#include <stdint.h>

using namespace nvcuda;

#define N_CELLS 16384
#define D_IN    512
#define D_HID   1024
#define D_OUT   512
#define G3H     3072
#define NF      8
#define FS      2048
#define NBIG    3328   // 3072 (gh) + 256 (H1)
#define NGI     3584   // 512 (soutput) + 3072 (gi)

// ---------------- device scratch (static, allocation-free) ----------------
__device__ __half d_wbig[(size_t)NBIG * D_HID];        // [W_hh^T ; W1^T] K-major
__device__ float  d_biasbig[NBIG];                     // [b_hh | xvec]
__device__ __half d_wgi[(size_t)NGI * 256];            // [[Wa2;-Wg2]^T ; W2W^T] K-major
__device__ float  d_bcat[NGI];                         // [bias2 | beff]
__device__ __half d_w2h[256 * 512];                    // [M=256][K=512] W2cat row-major
__device__ float  d_bias2[512];                        // ba2 - bg2
__device__ __half d_wih_t[(size_t)G3H * D_OUT];        // W_ih[:512]^T [3072][512]
__device__ __half d_hid_h[(size_t)N_CELLS * D_HID];    // fp16 hiddens
__device__ __half d_srelu_h[(size_t)N_CELLS * 256];    // fp16 relu acts (a|g)
__device__ __half d_soutput_h[(size_t)N_CELLS * 512];  // fp16 output = a - g
__device__ float  d_tension[N_CELLS];
__device__ float  d_ebuf[N_CELLS];
__device__ __half d_gi_h[(size_t)N_CELLS * G3H];       // fp16 gi preacts (no t-term)
__device__ __half d_gh_h[(size_t)N_CELLS * G3H];       // fp16 gh preacts
__device__ float  d_hpost[(size_t)N_CELLS * D_HID];
__device__ float  d_sumall[NF * D_HID];
__device__ float  d_sumpos[NF * D_HID];
__device__ float  d_sumneg[NF * D_HID];
__device__ float  d_meanp[D_HID];
__device__ float  d_meann[D_HID];
__device__ float  d_F[NF * D_HID];
__device__ float  d_gop[D_HID];
__device__ int    d_cntp[NF];
__device__ int    d_cntn[NF];
__device__ int    d_cnt_tot[2];
__device__ float  d_tsum;
__device__ float  d_sumexp;
__device__ float  d_cout[512];

// ---------------- cp.async helpers ----------------
__device__ __forceinline__ void cp16(uint32_t daddr, const void* src) {
    asm volatile("cp.async.cg.shared.global [%0], [%1], 16;" :: "r"(daddr), "l"(src));
}
__device__ __forceinline__ void cp_commit() {
    asm volatile("cp.async.commit_group;" ::: "memory");
}
template <int N>
__device__ __forceinline__ void cp_wait() {
    asm volatile("cp.async.wait_group %0;" :: "n"(N) : "memory");
}

__device__ __forceinline__ float fast_sigmoid(float x) {
    return 1.0f / (1.0f + __expf(-x));
}
__device__ __forceinline__ float fast_tanh(float x) {
    float a = fabsf(x);
    float e = __expf(-2.0f * a);
    float r = (1.0f - e) / (1.0f + e);
    return copysignf(r, x);
}

// ---------------- pipelined fp16 WMMA GEMM (proven config) ----------------
// C[M x Ntot] = A[M x K] (fp16, row-major) * Bt[Ntot x K] (fp16, K-major)^T
// Block tile 128x128, BK=32, 3-stage cp.async pipeline, 256 threads,
// warp grid 2x4 (warp tile 64x32), fp32 accumulate, 2 CTAs/SM.
// modes: 8=write half Ch, 16=skip fp32 C, 32=no bias,
//        4=fused gh+H1 epilogue, 64=fused soutput+gi epilogue
#define STAGE_H 10240   // halves per stage: A 128x40 + B 128x40

__global__ void __launch_bounds__(256, 2) gemm_fp16(
    const __half* __restrict__ A, int lda,
    const __half* __restrict__ Bt,
    float* __restrict__ C, __half* __restrict__ Ch, int ldc,
    int K, int mode,
    const float* __restrict__ bias)
{
    extern __shared__ __align__(16) char smem_raw[];
    __half* smem = (__half*)smem_raw;
    const uint32_t sbase = (uint32_t)__cvta_generic_to_shared(smem);

    const int tid  = threadIdx.x;
    const int bm   = blockIdx.y * 128;
    const int bn   = blockIdx.x * 128;
    const int warp = tid >> 5;
    const int wr   = warp & 1;   // 2 warp rows of 64
    const int wc   = warp >> 1;  // 4 warp cols of 32

    wmma::fragment<wmma::accumulator, 16, 16, 16, float> acc[4][2];
#pragma unroll
    for (int i = 0; i < 4; i++)
#pragma unroll
        for (int j = 0; j < 2; j++) wmma::fill_fragment(acc[i][j], 0.0f);

    const int crow = tid >> 1;           // 0..127
    const int ccol = (tid & 1) << 4;     // 0 or 16 (halves)

#define ISSUE(KT)                                                              \
    {                                                                          \
        uint32_t so = ((KT) % 3) * STAGE_H;                                    \
        int k0 = (KT) << 5;                                                    \
        _Pragma("unroll")                                                      \
        for (int h2 = 0; h2 < 2; h2++) {                                       \
            int cc = ccol + h2 * 8;                                            \
            cp16(sbase + (so + crow * 40 + cc) * 2,                            \
                 A + (size_t)(bm + crow) * lda + k0 + cc);                     \
            cp16(sbase + (so + 5120 + crow * 40 + cc) * 2,                     \
                 Bt + (size_t)(bn + crow) * K + k0 + cc);                      \
        }                                                                      \
        cp_commit();                                                           \
    }

#define MMA_TILE(KT)                                                           \
    {                                                                          \
        __half* As = smem + ((KT) % 3) * STAGE_H;                              \
        __half* Bs = As + 5120;                                                \
        _Pragma("unroll")                                                      \
        for (int kk = 0; kk < 32; kk += 16) {                                  \
            wmma::fragment<wmma::matrix_a, 16, 16, 16, __half, wmma::row_major> af[4]; \
            wmma::fragment<wmma::matrix_b, 16, 16, 16, __half, wmma::col_major> bf[2]; \
            _Pragma("unroll")                                                  \
            for (int i = 0; i < 4; i++)                                        \
                wmma::load_matrix_sync(af[i], As + (wr * 64 + i * 16) * 40 + kk, 40); \
            _Pragma("unroll")                                                  \
            for (int j = 0; j < 2; j++)                                        \
                wmma::load_matrix_sync(bf[j], Bs + (wc * 32 + j * 16) * 40 + kk, 40); \
            _Pragma("unroll")                                                  \
            for (int i = 0; i < 4; i++)                                        \
                _Pragma("unroll")                                              \
                for (int j = 0; j < 2; j++)                                    \
                    wmma::mma_sync(acc[i][j], af[i], bf[j], acc[i][j]);        \
        }                                                                      \
    }

    const int nk = K >> 5;
    ISSUE(0)
    ISSUE(1)

    for (int kt = 0; kt < nk - 1; kt++) {
        cp_wait<1>();
        __syncthreads();
        if (kt + 2 < nk) ISSUE(kt + 2)
        MMA_TILE(kt)
    }
    cp_wait<0>();
    __syncthreads();
    MMA_TILE(nk - 1)
#undef ISSUE
#undef MMA_TILE

    // epilogue in two 64-col halves staged through shared (floats, stride 72)
    float* Cs = (float*)smem;
#pragma unroll
    for (int h = 0; h < 2; h++) {
        __syncthreads();
        if ((wc >> 1) == h) {
            const int lc = (wc & 1) << 5;
#pragma unroll
            for (int i = 0; i < 4; i++)
#pragma unroll
                for (int j = 0; j < 2; j++)
                    wmma::store_matrix_sync(Cs + (wr * 64 + i * 16) * 72 + lc + j * 16,
                                            acc[i][j], 72, wmma::mem_row_major);
        }
        __syncthreads();
#pragma unroll
        for (int it = 0; it < 32; it++) {
            int idx = it * 256 + tid;
            int r = idx >> 6, c = idx & 63;
            int gr = bm + r, gc = bn + (h << 6) + c;
            float v = Cs[r * 72 + c];
            if (!(mode & 32)) v += bias[gc];
            if (mode & 4) {
                if (gc < G3H) d_gh_h[(size_t)gr * G3H + gc] = __float2half(v);
                else d_srelu_h[(size_t)gr * 256 + (gc - G3H)] =
                         __float2half(fmaxf(v, 0.0f));
            } else if (mode & 64) {
                if (gc < 512) d_soutput_h[(size_t)gr * 512 + gc] = __float2half(v);
                else d_gi_h[(size_t)gr * G3H + (gc - 512)] = __float2half(v);
            } else {
                if (!(mode & 16)) C[(size_t)gr * ldc + gc] = v;
                if (mode & 8)  Ch[(size_t)gr * ldc + gc] = __float2half(v);
            }
        }
    }
}

// ---------------- prep kernels ----------------
__global__ void cvt_half(const float* __restrict__ src, __half* __restrict__ dst) {
    size_t i = (size_t)blockIdx.x * 256 + threadIdx.x;
    float4 v = reinterpret_cast<const float4*>(src)[i];
    __half2* d = reinterpret_cast<__half2*>(dst) + i * 2;
    d[0] = __floats2half2_rn(v.x, v.y);
    d[1] = __floats2half2_rn(v.z, v.w);
}

// both weight transposes in one launch:
// blockIdx.y < 32: W_hh -> wbig (R=1024, C=3072); else W_ih -> wih_t (R=512, C=3072)
__global__ void transpose_both(const float* __restrict__ Whh, const float* __restrict__ Wih) {
    __shared__ float tile[32][33];
    int x = threadIdx.x, y = threadIdx.y;   // (32, 8)
    int c0 = blockIdx.x * 32;
    const float* src; __half* dst; int R, r0;
    if (blockIdx.y < 32) { src = Whh; dst = d_wbig;  R = 1024; r0 = blockIdx.y * 32; }
    else                 { src = Wih; dst = d_wih_t; R = 512;  r0 = (blockIdx.y - 32) * 32; }
#pragma unroll
    for (int i = 0; i < 32; i += 8)
        tile[y + i][x] = src[(size_t)(r0 + y + i) * 3072 + c0 + x];
    __syncthreads();
#pragma unroll
    for (int i = 0; i < 32; i += 8)
        dst[(size_t)(c0 + y + i) * R + r0 + x] = __float2half(tile[x][y + i]);
}

// one merged prep kernel (uniform 256 threads):
// blocks [0,1024):    w1t  -> wbig rows 3072..3327
// blocks [1024,1536): w2t  -> wgi rows 0..511 + w2h + bias2 + bcat[0..511]
// blocks [1536,1568): prep GEMV -> biasbig[3072..3327]
// blocks [1568,1696): init (zero sums/cout, seed out, biasbig[0..3071]=b_hh, scalars)
// blocks [1696,1704): count (self-contained per-faction reduction)
__global__ void prep_misc(
    const float* __restrict__ x,
    const float* __restrict__ Wa1, const float* __restrict__ ba1,
    const float* __restrict__ Wg1, const float* __restrict__ bg1,
    const float* __restrict__ Wa2, const float* __restrict__ ba2,
    const float* __restrict__ Wg2, const float* __restrict__ bg2,
    const float* __restrict__ b_hh, const float* __restrict__ bo,
    const int* __restrict__ pos, float* __restrict__ out)
{
    int b = blockIdx.x, tid = threadIdx.x;
    if (b < 1024) {                       // w1t
        int n = b >> 2;
        int k = (b & 3) * 256 + tid;
        float v = (n < 128) ? Wa1[(size_t)(512 + k) * 128 + n]
                            : Wg1[(size_t)(512 + k) * 128 + (n - 128)];
        d_wbig[(size_t)(G3H + n) * 1024 + k] = __float2half(v);
    } else if (b < 1536) {                // w2t
        int n = b - 1024;                 // 0..511
        int k = tid;                      // 0..255
        float v = (k < 128) ? Wa2[(size_t)k * 512 + n]
                            : -Wg2[(size_t)(k - 128) * 512 + n];
        d_wgi[(size_t)n * 256 + k] = __float2half(v);
        d_w2h[(size_t)k * 512 + n] = __float2half(v);
        if (k == 0) { float bb = ba2[n] - bg2[n]; d_bias2[n] = bb; d_bcat[n] = bb; }
    } else if (b < 1568) {                // prep GEMV: 8 warps -> 8 cols per block
        int n = ((b - 1536) << 3) + (tid >> 5);   // 0..255
        int lane = tid & 31;
        const float* W = (n < 128) ? Wa1 : Wg1;
        int col = n & 127;
        float s = 0.0f;
        for (int k = lane; k < D_IN; k += 32) s += x[k] * W[k * 128 + col];
#pragma unroll
        for (int off = 16; off; off >>= 1) s += __shfl_xor_sync(0xffffffffu, s, off);
        if (lane == 0) d_biasbig[G3H + n] = s + ((n < 128) ? ba1[col] : bg1[col]);
    } else if (b < 1696) {                // init
        int gid = (b - 1568) * 256 + tid; // 0..32767
        if (gid < NF * D_HID) {
            d_sumall[gid] = 0.0f; d_sumpos[gid] = 0.0f; d_sumneg[gid] = 0.0f;
        }
        if (gid < G3H) d_biasbig[gid] = b_hh[gid];
        if (gid < 512) { d_cout[gid] = 0.0f; out[gid] = bo[gid]; }
        if (gid == 600) { d_tsum = 0.0f; d_sumexp = 0.0f; }
    } else {                              // count: block per faction
        int f = b - 1696;                 // 0..7
        int cp = 0, cn = 0;
        for (int r = tid; r < FS; r += 256) {
            int p = pos[f * FS + r];
            cp += (p > 0); cn += (p < 0);
        }
#pragma unroll
        for (int off = 16; off; off >>= 1) {
            cp += __shfl_xor_sync(0xffffffffu, cp, off);
            cn += __shfl_xor_sync(0xffffffffu, cn, off);
        }
        __shared__ int scp[8], scn[8];
        if ((tid & 31) == 0) { scp[tid >> 5] = cp; scn[tid >> 5] = cn; }
        __syncthreads();
        if (tid == 0) {
            int a = 0, c = 0;
            for (int w = 0; w < 8; w++) { a += scp[w]; c += scn[w]; }
            d_cntp[f] = a; d_cntn[f] = c;
        }
    }
}

// bcat[512+c] = b_ih[c] + sum_o bias2[o] * W_ih[o][c]   (warp per c)
__global__ void beff_kernel(const float* __restrict__ b_ih) {
    int c = (blockIdx.x << 3) + (threadIdx.x >> 5);   // grid 384 x 256 -> c 0..3071
    int lane = threadIdx.x & 31;
    const __half* w = d_wih_t + (size_t)c * 512;
    float s = 0.0f;
    for (int o = lane; o < 512; o += 32) s += d_bias2[o] * __half2float(w[o]);
#pragma unroll
    for (int off = 16; off; off >>= 1) s += __shfl_xor_sync(0xffffffffu, s, off);
    if (lane == 0) d_bcat[512 + c] = s + b_ih[c];
}

// ---------------- elementwise / reduction kernels ----------------
// tension + exp + sums in one pass (no max-subtraction; tension is O(1))
__global__ void tension_kernel() {
    int row  = blockIdx.x * 8 + (threadIdx.x >> 5);
    int lane = threadIdx.x & 31;
    const __half2* o = reinterpret_cast<const __half2*>(d_soutput_h + (size_t)row * 512);
    float s = 0.0f;
    for (int c = lane; c < 256; c += 32) {
        float2 v = __half22float2(o[c]);
        s += v.x * v.x + v.y * v.y;
    }
#pragma unroll
    for (int off = 16; off; off >>= 1) s += __shfl_xor_sync(0xffffffffu, s, off);
    __shared__ float wsum[8];
    __shared__ float wexp[8];
    float t = s * (1.0f / 512.0f);
    float e = __expf(t);
    if (lane == 0) {
        d_tension[row] = t;
        d_ebuf[row] = e;
        wsum[threadIdx.x >> 5] = t;
        wexp[threadIdx.x >> 5] = e;
    }
    __syncthreads();
    if (threadIdx.x == 0) {
        float a = 0.0f, m = 0.0f;
        for (int w = 0; w < 8; w++) { a += wsum[w]; m += wexp[w]; }
        atomicAdd(&d_tsum, a);
        atomicAdd(&d_sumexp, m);
    }
}

// GRU combine + wealth mod + clip; half2 vectorized; adds tension rank-1 term
__global__ void gru_kernel(const float* __restrict__ hid, const float* __restrict__ wealth,
                           const float* __restrict__ wih512) {
    size_t t = (size_t)blockIdx.x * 256 + threadIdx.x;   // 0 .. 8.39M
    int i  = (int)(t >> 9);          // row
    int j2 = (int)(t & 511);         // half2 index within 1024-wide row
    const __half2* gi = reinterpret_cast<const __half2*>(d_gi_h + (size_t)i * G3H);
    const __half2* gh = reinterpret_cast<const __half2*>(d_gh_h + (size_t)i * G3H);
    float2 gir = __half22float2(gi[j2]);
    float2 giz = __half22float2(gi[j2 + 512]);
    float2 gin = __half22float2(gi[j2 + 1024]);
    float2 ghr = __half22float2(gh[j2]);
    float2 ghz = __half22float2(gh[j2 + 512]);
    float2 ghn = __half22float2(gh[j2 + 1024]);
    float2 h = *reinterpret_cast<const float2*>(hid + (size_t)i * 1024 + j2 * 2);
    float tn = d_tension[i];
    float2 wr = *reinterpret_cast<const float2*>(wih512 + j2 * 2);
    float2 wz = *reinterpret_cast<const float2*>(wih512 + 1024 + j2 * 2);
    float2 wn = *reinterpret_cast<const float2*>(wih512 + 2048 + j2 * 2);
    float w = wealth[i];
    float mod = 0.9f + 0.1f * fminf(fmaxf(w, 0.1f), 2.0f);

    float r0 = fast_sigmoid(gir.x + ghr.x + tn * wr.x);
    float z0 = fast_sigmoid(giz.x + ghz.x + tn * wz.x);
    float n0 = fast_tanh(gin.x + tn * wn.x + r0 * ghn.x);
    float nh0 = fminf(fmaxf(((1.0f - z0) * n0 + z0 * h.x) * mod, -10.0f), 10.0f);

    float r1 = fast_sigmoid(gir.y + ghr.y + tn * wr.y);
    float z1 = fast_sigmoid(giz.y + ghz.y + tn * wz.y);
    float n1 = fast_tanh(gin.y + tn * wn.y + r1 * ghn.y);
    float nh1 = fminf(fmaxf(((1.0f - z1) * n1 + z1 * h.y) * mod, -10.0f), 10.0f);

    *reinterpret_cast<float2*>(d_hpost + (size_t)i * 1024 + j2 * 2) = make_float2(nh0, nh1);
}

// per-faction column sums, row-chunked: grid (8, 8, 8)
__global__ void stats_kernel(const int* __restrict__ pos) {
    int f = blockIdx.x;                          // faction
    int j = blockIdx.y * 128 + threadIdx.x;      // column
    int r0 = blockIdx.z * 256;                   // row chunk within faction
    int base = f * FS + r0;
    float sa = 0.0f, sp = 0.0f, sn = 0.0f;
    for (int r = 0; r < 256; r++) {
        float v = d_hpost[(size_t)(base + r) * D_HID + j];
        int p = pos[base + r];
        sa += v;
        if (p > 0) sp += v; else if (p < 0) sn += v;
    }
    atomicAdd(&d_sumall[f * D_HID + j], sa);
    atomicAdd(&d_sumpos[f * D_HID + j], sp);
    atomicAdd(&d_sumneg[f * D_HID + j], sn);
}

__global__ void statsfinal_kernel() {
    int j = threadIdx.x;           // 0..1023
    int cp = 0, cn = 0;
    for (int f = 0; f < NF; f++) { cp += d_cntp[f]; cn += d_cntn[f]; }
    float sp = 0.0f, sn = 0.0f;
    for (int f = 0; f < NF; f++) { sp += d_sumpos[f * D_HID + j]; sn += d_sumneg[f * D_HID + j]; }
    float mp = sp / (float)max(cp, 1);
    float mn = sn / (float)max(cn, 1);
    d_meanp[j] = mp; d_meann[j] = mn;
    float g = 0.0f;
    for (int f = 0; f < NF; f++) {
        float adj = d_sumall[f * D_HID + j];
        if (cp >= 2) adj += 0.1f * ((float)d_cntp[f] * mp - d_sumpos[f * D_HID + j]);
        if (cn >= 2) adj += 0.1f * ((float)d_cntn[f] * mn - d_sumneg[f * D_HID + j]);
        float F = adj * (1.0f / (float)FS);
        d_F[f * D_HID + j] = F;
        g += F;
    }
    d_gop[j] = g * (1.0f / (float)NF);
    if (j == 0) { d_cnt_tot[0] = cp; d_cnt_tot[1] = cn; }
}

// apply syncs + debate; float4 per thread
__global__ void final_kernel(const int* __restrict__ pos, const int* __restrict__ step,
                             float* __restrict__ out) {
    size_t t = (size_t)blockIdx.x * 256 + threadIdx.x;   // 0 .. 4.19M
    int i = (int)(t >> 8);
    int j = (int)(t & 255) * 4;
    float4 h4 = *reinterpret_cast<const float4*>(d_hpost + (size_t)i * 1024 + j);
    int p = pos[i];
    int cp = d_cnt_tot[0], cn = d_cnt_tot[1];
    float* hv = (float*)&h4;
    if (p > 0 && cp >= 2) {
        const float4 m4 = *reinterpret_cast<const float4*>(d_meanp + j);
        const float* mv = (const float*)&m4;
#pragma unroll
        for (int q = 0; q < 4; q++) hv[q] = 0.9f * hv[q] + 0.1f * mv[q];
    } else if (p < 0 && cn >= 2) {
        const float4 m4 = *reinterpret_cast<const float4*>(d_meann + j);
        const float* mv = (const float*)&m4;
#pragma unroll
        for (int q = 0; q < 4; q++) hv[q] = 0.9f * hv[q] + 0.1f * mv[q];
    }
    int f = i >> 11;
    const float4 F4 = *reinterpret_cast<const float4*>(d_F + f * D_HID + j);
    const float* Fv = (const float*)&F4;
#pragma unroll
    for (int q = 0; q < 4; q++) hv[q] = 0.85f * hv[q] + 0.15f * Fv[q];
    if (*step > 5 && (i & (FS - 1)) < (FS / 4)) {
        const float4 g4 = *reinterpret_cast<const float4*>(d_gop + j);
        const float* gv = (const float*)&g4;
#pragma unroll
        for (int q = 0; q < 4; q++) hv[q] = 0.85f * hv[q] + 0.15f * gv[q];
    }
    float* o = out + 513 + (size_t)i * 1024 + j;
#pragma unroll
    for (int q = 0; q < 4; q++) o[q] = hv[q];
}

// combined_out = sum_i softmax(tension)_i * output[i,:]; 256 blocks x 64 rows
__global__ void wsum_kernel() {
    int r0 = blockIdx.x * 64;
    float inv = 1.0f / d_sumexp;
    int t = threadIdx.x;
    float c0 = 0.0f, c1 = 0.0f;
    for (int r = r0; r < r0 + 64; r++) {
        float w = d_ebuf[r] * inv;
        const __half* o = d_soutput_h + (size_t)r * 512;
        c0 += w * __half2float(o[t]);
        c1 += w * __half2float(o[t + 256]);
    }
    atomicAdd(&d_cout[t], c0);
    atomicAdd(&d_cout[t + 256], c1);
}

// split-K GEMV: out[t] += sum_{k in chunk} cout[k]*Wo[k][t]; bias seeded in prep
__global__ void pred_kernel(const float* __restrict__ Wo, float* __restrict__ out) {
    __shared__ float co[64];
    int b = blockIdx.x;      // 0..7
    int t = threadIdx.x;     // 0..511
    if (t < 64) co[t] = d_cout[b * 64 + t];
    __syncthreads();
    float s = 0.0f;
#pragma unroll 8
    for (int k = 0; k < 64; k++) s += co[k] * Wo[(size_t)(b * 64 + k) * 512 + t];
    atomicAdd(&out[t], s);
    if (b == 0 && t == 0) out[512] = d_tsum * (1.0f / (float)N_CELLS);
}

// ---------------- launch ----------------
extern "C" void kernel_launch(void* const* d_in, const int* in_sizes, int n_in,
                              void* d_out, int out_size) {
    const float* x        = (const float*)d_in[0];
    const float* hiddens  = (const float*)d_in[1];
    const float* wealth   = (const float*)d_in[2];
    const float* Wa1      = (const float*)d_in[3];
    const float* ba1      = (const float*)d_in[4];
    const float* Wa2      = (const float*)d_in[5];
    const float* ba2      = (const float*)d_in[6];
    const float* Wg1      = (const float*)d_in[7];
    const float* bg1      = (const float*)d_in[8];
    const float* Wg2      = (const float*)d_in[9];
    const float* bg2      = (const float*)d_in[10];
    const float* W_ih     = (const float*)d_in[11];
    const float* W_hh     = (const float*)d_in[12];
    const float* b_ih     = (const float*)d_in[13];
    const float* b_hh     = (const float*)d_in[14];
    const float* Wo       = (const float*)d_in[15];
    const float* bo       = (const float*)d_in[16];
    const int*   positions= (const int*)d_in[17];
    const int*   step     = (const int*)d_in[18];
    float* out = (float*)d_out;

    void *p_srelu_h, *p_w2h, *p_wbig, *p_biasbig, *p_wgi, *p_bcat;
    void *p_hid_h, *p_wih_t;
    cudaGetSymbolAddress(&p_srelu_h,   d_srelu_h);
    cudaGetSymbolAddress(&p_w2h,       d_w2h);
    cudaGetSymbolAddress(&p_wbig,      d_wbig);
    cudaGetSymbolAddress(&p_biasbig,   d_biasbig);
    cudaGetSymbolAddress(&p_wgi,       d_wgi);
    cudaGetSymbolAddress(&p_bcat,      d_bcat);
    cudaGetSymbolAddress(&p_hid_h,     d_hid_h);
    cudaGetSymbolAddress(&p_wih_t,     d_wih_t);

    const int SMEM_BYTES = 3 * STAGE_H * 2;   // 61440
    cudaFuncSetAttribute(gemm_fp16,
                         cudaFuncAttributeMaxDynamicSharedMemorySize, SMEM_BYTES);

    prep_misc<<<1704, 256>>>(x, Wa1, ba1, Wg1, bg1, Wa2, ba2, Wg2, bg2,
                             b_hh, bo, positions, out);                      // 1
    transpose_both<<<dim3(96, 48), dim3(32, 8)>>>(W_hh, W_ih);               // 2
    cvt_half<<<16384, 256>>>(hiddens, (__half*)p_hid_h);                     // 3

    // fused: [gh | H1] = hid @ [W_hh | W1] + [b_hh | xvec]  [112 GF]
    gemm_fp16<<<dim3(26, 128), 256, SMEM_BYTES>>>(                           // 4
        (const __half*)p_hid_h, 1024, (const __half*)p_wbig,
        nullptr, nullptr, 0, 1024, 4, (const float*)p_biasbig);

    // W2W^T [3072 x 256] = wih_t @ w2h^T -> wgi rows 512..3583
    gemm_fp16<<<dim3(2, 24), 256, SMEM_BYTES>>>(                             // 5
        (const __half*)p_wih_t, 512, (const __half*)p_w2h,
        nullptr, (__half*)p_wgi + (size_t)512 * 256, 256, 512, 8 | 16 | 32,
        nullptr);

    beff_kernel<<<384, 256>>>(b_ih);                                         // 6

    // fused: [soutput | gi] = H1 @ [W2cat | W2W] + [bias2 | beff]  [30 GF, K=256]
    gemm_fp16<<<dim3(28, 128), 256, SMEM_BYTES>>>(                           // 7
        (const __half*)p_srelu_h, 256, (const __half*)p_wgi,
        nullptr, nullptr, 0, 256, 64, (const float*)p_bcat);

    tension_kernel<<<2048, 256>>>();                                         // 8
    gru_kernel<<<32768, 256>>>(hiddens, wealth, W_ih + (size_t)512 * 3072);  // 9
    stats_kernel<<<dim3(8, 8, 8), 128>>>(positions);                         // 10
    statsfinal_kernel<<<1, 1024>>>();                                        // 11
    final_kernel<<<16384, 256>>>(positions, step, out);                      // 12
    wsum_kernel<<<256, 256>>>();                                             // 13
    pred_kernel<<<8, 512>>>(Wo, out);                                        // 14
}

// round 17
// speedup vs baseline: 1.5900x; 1.0100x over previous
#include <cuda_runtime.h>
#include <cuda_fp16.h>
#include <mma.h>
#include <math.h>
#include <stdint.h>

using namespace nvcuda;

#define N_CELLS 16384
#define D_IN    512
#define D_HID   1024
#define D_OUT   512
#define G3H     3072
#define NF      8
#define FS      2048
#define NBIG    3328   // 3072 (gh) + 256 (H1)
#define NGI     3584   // 512 (soutput) + 3072 (gi)

// ---------------- device scratch (static, allocation-free) ----------------
__device__ __half d_wbig[(size_t)NBIG * D_HID];        // [W_hh^T ; W1^T] K-major
__device__ float  d_biasbig[NBIG];                     // [b_hh | xvec]
__device__ __half d_wgi[(size_t)NGI * 256];            // [[Wa2;-Wg2]^T ; W2W^T] K-major
__device__ float  d_bcat[NGI];                         // [bias2 | beff]
__device__ __half d_w2h[256 * 512];                    // [M=256][K=512] W2cat row-major
__device__ float  d_bias2[512];                        // ba2 - bg2
__device__ __half d_wih_t[(size_t)G3H * D_OUT];        // W_ih[:512]^T [3072][512]
__device__ __half d_hid_h[(size_t)N_CELLS * D_HID];    // fp16 hiddens
__device__ __half d_srelu_h[(size_t)N_CELLS * 256];    // fp16 relu acts (a|g)
__device__ __half d_soutput_h[(size_t)N_CELLS * 512];  // fp16 output = a - g
__device__ float  d_tension[N_CELLS];
__device__ float  d_ebuf[N_CELLS];
__device__ __half d_gi_h[(size_t)N_CELLS * G3H];       // fp16 gi preacts (no t-term)
__device__ __half d_gh_h[(size_t)N_CELLS * G3H];       // fp16 gh preacts
__device__ __half d_hpost_h[(size_t)N_CELLS * D_HID];  // fp16 post-GRU state
__device__ float  d_sumall[NF * D_HID];
__device__ float  d_sumpos[NF * D_HID];
__device__ float  d_sumneg[NF * D_HID];
__device__ float  d_meanp[D_HID];
__device__ float  d_meann[D_HID];
__device__ float  d_F[NF * D_HID];
__device__ float  d_gop[D_HID];
__device__ int    d_cntp[NF];
__device__ int    d_cntn[NF];
__device__ int    d_cnt_tot[2];
__device__ float  d_tsum;
__device__ float  d_sumexp;
__device__ float  d_cout[512];

// ---------------- cp.async helpers ----------------
__device__ __forceinline__ void cp16(uint32_t daddr, const void* src) {
    asm volatile("cp.async.cg.shared.global [%0], [%1], 16;" :: "r"(daddr), "l"(src));
}
__device__ __forceinline__ void cp_commit() {
    asm volatile("cp.async.commit_group;" ::: "memory");
}
template <int N>
__device__ __forceinline__ void cp_wait() {
    asm volatile("cp.async.wait_group %0;" :: "n"(N) : "memory");
}

__device__ __forceinline__ float fast_sigmoid(float x) {
    return 1.0f / (1.0f + __expf(-x));
}
__device__ __forceinline__ float fast_tanh(float x) {
    float a = fabsf(x);
    float e = __expf(-2.0f * a);
    float r = (1.0f - e) / (1.0f + e);
    return copysignf(r, x);
}

// ---------------- pipelined fp16 WMMA GEMM (proven config) ----------------
// C[M x Ntot] = A[M x K] (fp16, row-major) * Bt[Ntot x K] (fp16, K-major)^T
// Block tile 128x128, BK=32, 3-stage cp.async pipeline, 256 threads,
// warp grid 2x4 (warp tile 64x32), fp32 accumulate, 2 CTAs/SM.
// modes: 8=write half Ch, 16=skip fp32 C, 32=no bias,
//        4=fused gh+H1 epilogue, 64=fused soutput+gi epilogue
#define STAGE_H 10240   // halves per stage: A 128x40 + B 128x40

__global__ void __launch_bounds__(256, 2) gemm_fp16(
    const __half* __restrict__ A, int lda,
    const __half* __restrict__ Bt,
    float* __restrict__ C, __half* __restrict__ Ch, int ldc,
    int K, int mode,
    const float* __restrict__ bias)
{
    extern __shared__ __align__(16) char smem_raw[];
    __half* smem = (__half*)smem_raw;
    const uint32_t sbase = (uint32_t)__cvta_generic_to_shared(smem);

    const int tid  = threadIdx.x;
    const int bm   = blockIdx.y * 128;
    const int bn   = blockIdx.x * 128;
    const int warp = tid >> 5;
    const int wr   = warp & 1;   // 2 warp rows of 64
    const int wc   = warp >> 1;  // 4 warp cols of 32

    wmma::fragment<wmma::accumulator, 16, 16, 16, float> acc[4][2];
#pragma unroll
    for (int i = 0; i < 4; i++)
#pragma unroll
        for (int j = 0; j < 2; j++) wmma::fill_fragment(acc[i][j], 0.0f);

    const int crow = tid >> 1;           // 0..127
    const int ccol = (tid & 1) << 4;     // 0 or 16 (halves)

#define ISSUE(KT)                                                              \
    {                                                                          \
        uint32_t so = ((KT) % 3) * STAGE_H;                                    \
        int k0 = (KT) << 5;                                                    \
        _Pragma("unroll")                                                      \
        for (int h2 = 0; h2 < 2; h2++) {                                       \
            int cc = ccol + h2 * 8;                                            \
            cp16(sbase + (so + crow * 40 + cc) * 2,                            \
                 A + (size_t)(bm + crow) * lda + k0 + cc);                     \
            cp16(sbase + (so + 5120 + crow * 40 + cc) * 2,                     \
                 Bt + (size_t)(bn + crow) * K + k0 + cc);                      \
        }                                                                      \
        cp_commit();                                                           \
    }

#define MMA_TILE(KT)                                                           \
    {                                                                          \
        __half* As = smem + ((KT) % 3) * STAGE_H;                              \
        __half* Bs = As + 5120;                                                \
        _Pragma("unroll")                                                      \
        for (int kk = 0; kk < 32; kk += 16) {                                  \
            wmma::fragment<wmma::matrix_a, 16, 16, 16, __half, wmma::row_major> af[4]; \
            wmma::fragment<wmma::matrix_b, 16, 16, 16, __half, wmma::col_major> bf[2]; \
            _Pragma("unroll")                                                  \
            for (int i = 0; i < 4; i++)                                        \
                wmma::load_matrix_sync(af[i], As + (wr * 64 + i * 16) * 40 + kk, 40); \
            _Pragma("unroll")                                                  \
            for (int j = 0; j < 2; j++)                                        \
                wmma::load_matrix_sync(bf[j], Bs + (wc * 32 + j * 16) * 40 + kk, 40); \
            _Pragma("unroll")                                                  \
            for (int i = 0; i < 4; i++)                                        \
                _Pragma("unroll")                                              \
                for (int j = 0; j < 2; j++)                                    \
                    wmma::mma_sync(acc[i][j], af[i], bf[j], acc[i][j]);        \
        }                                                                      \
    }

    const int nk = K >> 5;
    ISSUE(0)
    ISSUE(1)

    for (int kt = 0; kt < nk - 1; kt++) {
        cp_wait<1>();
        __syncthreads();
        if (kt + 2 < nk) ISSUE(kt + 2)
        MMA_TILE(kt)
    }
    cp_wait<0>();
    __syncthreads();
    MMA_TILE(nk - 1)
#undef ISSUE
#undef MMA_TILE

    // epilogue in two 64-col halves staged through shared (floats, stride 72)
    float* Cs = (float*)smem;
#pragma unroll
    for (int h = 0; h < 2; h++) {
        __syncthreads();
        if ((wc >> 1) == h) {
            const int lc = (wc & 1) << 5;
#pragma unroll
            for (int i = 0; i < 4; i++)
#pragma unroll
                for (int j = 0; j < 2; j++)
                    wmma::store_matrix_sync(Cs + (wr * 64 + i * 16) * 72 + lc + j * 16,
                                            acc[i][j], 72, wmma::mem_row_major);
        }
        __syncthreads();
#pragma unroll
        for (int it = 0; it < 32; it++) {
            int idx = it * 256 + tid;
            int r = idx >> 6, c = idx & 63;
            int gr = bm + r, gc = bn + (h << 6) + c;
            float v = Cs[r * 72 + c];
            if (!(mode & 32)) v += bias[gc];
            if (mode & 4) {
                if (gc < G3H) d_gh_h[(size_t)gr * G3H + gc] = __float2half(v);
                else d_srelu_h[(size_t)gr * 256 + (gc - G3H)] =
                         __float2half(fmaxf(v, 0.0f));
            } else if (mode & 64) {
                if (gc < 512) d_soutput_h[(size_t)gr * 512 + gc] = __float2half(v);
                else d_gi_h[(size_t)gr * G3H + (gc - 512)] = __float2half(v);
            } else {
                if (!(mode & 16)) C[(size_t)gr * ldc + gc] = v;
                if (mode & 8)  Ch[(size_t)gr * ldc + gc] = __float2half(v);
            }
        }
    }
}

// ---------------- mega prep kernel (one launch) ----------------
// blocks [0,16384):        cvt hiddens -> hid_h (fp16)
// blocks [16384,20992):    both weight transposes (96 x 48 tiles)
// blocks [20992,22016):    w1t -> wbig rows 3072..3327
// blocks [22016,22528):    w2t -> wgi rows 0..511 + w2h + bias2 + bcat[0..511]
// blocks [22528,22560):    prep GEMV -> biasbig[3072..3327]
// blocks [22560,22688):    init (zero sums/cout, seed out, biasbig[0..3071]=b_hh)
// blocks [22688,22696):    count (per-faction reduction)
__global__ void prep_all(
    const float* __restrict__ hiddens,
    const float* __restrict__ Whh, const float* __restrict__ Wih,
    const float* __restrict__ x,
    const float* __restrict__ Wa1, const float* __restrict__ ba1,
    const float* __restrict__ Wg1, const float* __restrict__ bg1,
    const float* __restrict__ Wa2, const float* __restrict__ ba2,
    const float* __restrict__ Wg2, const float* __restrict__ bg2,
    const float* __restrict__ b_hh, const float* __restrict__ bo,
    const int* __restrict__ pos, float* __restrict__ out)
{
    int b = blockIdx.x, tid = threadIdx.x;
    if (b < 16384) {                      // cvt hiddens -> fp16
        size_t i = (size_t)b * 256 + tid;
        float4 v = reinterpret_cast<const float4*>(hiddens)[i];
        __half2* d = reinterpret_cast<__half2*>(d_hid_h) + i * 2;
        d[0] = __floats2half2_rn(v.x, v.y);
        d[1] = __floats2half2_rn(v.z, v.w);
    } else if (b < 20992) {               // transposes
        __shared__ float tile[32][33];
        int bb = b - 16384;
        int bx = bb % 96, by = bb / 96;   // by 0..47
        int xx = tid & 31, yy = tid >> 5; // (32, 8)
        int c0 = bx * 32;
        const float* src; __half* dst; int R, r0;
        if (by < 32) { src = Whh; dst = d_wbig;  R = 1024; r0 = by * 32; }
        else         { src = Wih; dst = d_wih_t; R = 512;  r0 = (by - 32) * 32; }
#pragma unroll
        for (int i = 0; i < 32; i += 8)
            tile[yy + i][xx] = src[(size_t)(r0 + yy + i) * 3072 + c0 + xx];
        __syncthreads();
#pragma unroll
        for (int i = 0; i < 32; i += 8)
            dst[(size_t)(c0 + yy + i) * R + r0 + xx] = __float2half(tile[xx][yy + i]);
    } else if (b < 22016) {               // w1t
        int bb = b - 20992;
        int n = bb >> 2;
        int k = (bb & 3) * 256 + tid;
        float v = (n < 128) ? Wa1[(size_t)(512 + k) * 128 + n]
                            : Wg1[(size_t)(512 + k) * 128 + (n - 128)];
        d_wbig[(size_t)(G3H + n) * 1024 + k] = __float2half(v);
    } else if (b < 22528) {               // w2t
        int n = b - 22016;                // 0..511
        int k = tid;                      // 0..255
        float v = (k < 128) ? Wa2[(size_t)k * 512 + n]
                            : -Wg2[(size_t)(k - 128) * 512 + n];
        d_wgi[(size_t)n * 256 + k] = __float2half(v);
        d_w2h[(size_t)k * 512 + n] = __float2half(v);
        if (k == 0) { float bb2 = ba2[n] - bg2[n]; d_bias2[n] = bb2; d_bcat[n] = bb2; }
    } else if (b < 22560) {               // prep GEMV (8 warps -> 8 cols)
        int n = ((b - 22528) << 3) + (tid >> 5);   // 0..255
        int lane = tid & 31;
        const float* W = (n < 128) ? Wa1 : Wg1;
        int col = n & 127;
        float s = 0.0f;
        for (int k = lane; k < D_IN; k += 32) s += x[k] * W[k * 128 + col];
#pragma unroll
        for (int off = 16; off; off >>= 1) s += __shfl_xor_sync(0xffffffffu, s, off);
        if (lane == 0) d_biasbig[G3H + n] = s + ((n < 128) ? ba1[col] : bg1[col]);
    } else if (b < 22688) {               // init
        int gid = (b - 22560) * 256 + tid; // 0..32767
        if (gid < NF * D_HID) {
            d_sumall[gid] = 0.0f; d_sumpos[gid] = 0.0f; d_sumneg[gid] = 0.0f;
        }
        if (gid < G3H) d_biasbig[gid] = b_hh[gid];
        if (gid < 512) { d_cout[gid] = 0.0f; out[gid] = bo[gid]; }
        if (gid == 600) { d_tsum = 0.0f; d_sumexp = 0.0f; }
    } else {                              // count: block per faction
        int f = b - 22688;                // 0..7
        int cp = 0, cn = 0;
        for (int r = tid; r < FS; r += 256) {
            int p = pos[f * FS + r];
            cp += (p > 0); cn += (p < 0);
        }
#pragma unroll
        for (int off = 16; off; off >>= 1) {
            cp += __shfl_xor_sync(0xffffffffu, cp, off);
            cn += __shfl_xor_sync(0xffffffffu, cn, off);
        }
        __shared__ int scp[8], scn[8];
        if ((tid & 31) == 0) { scp[tid >> 5] = cp; scn[tid >> 5] = cn; }
        __syncthreads();
        if (tid == 0) {
            int a = 0, c = 0;
            for (int w = 0; w < 8; w++) { a += scp[w]; c += scn[w]; }
            d_cntp[f] = a; d_cntn[f] = c;
        }
    }
}

// bcat[512+c] = b_ih[c] + sum_o bias2[o] * W_ih[o][c]   (warp per c)
__global__ void beff_kernel(const float* __restrict__ b_ih) {
    int c = (blockIdx.x << 3) + (threadIdx.x >> 5);   // grid 384 x 256 -> c 0..3071
    int lane = threadIdx.x & 31;
    const __half* w = d_wih_t + (size_t)c * 512;
    float s = 0.0f;
    for (int o = lane; o < 512; o += 32) s += d_bias2[o] * __half2float(w[o]);
#pragma unroll
    for (int off = 16; off; off >>= 1) s += __shfl_xor_sync(0xffffffffu, s, off);
    if (lane == 0) d_bcat[512 + c] = s + b_ih[c];
}

// ---------------- elementwise / reduction kernels ----------------
__global__ void tension_kernel() {
    int row  = blockIdx.x * 8 + (threadIdx.x >> 5);
    int lane = threadIdx.x & 31;
    const __half2* o = reinterpret_cast<const __half2*>(d_soutput_h + (size_t)row * 512);
    float s = 0.0f;
    for (int c = lane; c < 256; c += 32) {
        float2 v = __half22float2(o[c]);
        s += v.x * v.x + v.y * v.y;
    }
#pragma unroll
    for (int off = 16; off; off >>= 1) s += __shfl_xor_sync(0xffffffffu, s, off);
    __shared__ float wsum[8];
    __shared__ float wexp[8];
    float t = s * (1.0f / 512.0f);
    float e = __expf(t);
    if (lane == 0) {
        d_tension[row] = t;
        d_ebuf[row] = e;
        wsum[threadIdx.x >> 5] = t;
        wexp[threadIdx.x >> 5] = e;
    }
    __syncthreads();
    if (threadIdx.x == 0) {
        float a = 0.0f, m = 0.0f;
        for (int w = 0; w < 8; w++) { a += wsum[w]; m += wexp[w]; }
        atomicAdd(&d_tsum, a);
        atomicAdd(&d_sumexp, m);
    }
}

// GRU combine + wealth mod + clip; fp16 in/out; adds tension rank-1 term
__global__ void gru_kernel(const float* __restrict__ wealth,
                           const float* __restrict__ wih512) {
    size_t t = (size_t)blockIdx.x * 256 + threadIdx.x;   // 0 .. 8.39M
    int i  = (int)(t >> 9);          // row
    int j2 = (int)(t & 511);         // half2 index within 1024-wide row
    const __half2* gi = reinterpret_cast<const __half2*>(d_gi_h + (size_t)i * G3H);
    const __half2* gh = reinterpret_cast<const __half2*>(d_gh_h + (size_t)i * G3H);
    float2 gir = __half22float2(gi[j2]);
    float2 giz = __half22float2(gi[j2 + 512]);
    float2 gin = __half22float2(gi[j2 + 1024]);
    float2 ghr = __half22float2(gh[j2]);
    float2 ghz = __half22float2(gh[j2 + 512]);
    float2 ghn = __half22float2(gh[j2 + 1024]);
    float2 h = __half22float2(
        reinterpret_cast<const __half2*>(d_hid_h + (size_t)i * 1024)[j2]);
    float tn = d_tension[i];
    float2 wr = *reinterpret_cast<const float2*>(wih512 + j2 * 2);
    float2 wz = *reinterpret_cast<const float2*>(wih512 + 1024 + j2 * 2);
    float2 wn = *reinterpret_cast<const float2*>(wih512 + 2048 + j2 * 2);
    float w = wealth[i];
    float mod = 0.9f + 0.1f * fminf(fmaxf(w, 0.1f), 2.0f);

    float r0 = fast_sigmoid(gir.x + ghr.x + tn * wr.x);
    float z0 = fast_sigmoid(giz.x + ghz.x + tn * wz.x);
    float n0 = fast_tanh(gin.x + tn * wn.x + r0 * ghn.x);
    float nh0 = fminf(fmaxf(((1.0f - z0) * n0 + z0 * h.x) * mod, -10.0f), 10.0f);

    float r1 = fast_sigmoid(gir.y + ghr.y + tn * wr.y);
    float z1 = fast_sigmoid(giz.y + ghz.y + tn * wz.y);
    float n1 = fast_tanh(gin.y + tn * wn.y + r1 * ghn.y);
    float nh1 = fminf(fmaxf(((1.0f - z1) * n1 + z1 * h.y) * mod, -10.0f), 10.0f);

    reinterpret_cast<__half2*>(d_hpost_h + (size_t)i * 1024)[j2] =
        __floats2half2_rn(nh0, nh1);
}

// per-faction column sums (fp16 source), row-chunked: grid (8, 8, 8)
__global__ void stats_kernel(const int* __restrict__ pos) {
    int f = blockIdx.x;
    int j = blockIdx.y * 128 + threadIdx.x;
    int r0 = blockIdx.z * 256;
    int base = f * FS + r0;
    float sa = 0.0f, sp = 0.0f, sn = 0.0f;
    for (int r = 0; r < 256; r++) {
        float v = __half2float(d_hpost_h[(size_t)(base + r) * D_HID + j]);
        int p = pos[base + r];
        sa += v;
        if (p > 0) sp += v; else if (p < 0) sn += v;
    }
    atomicAdd(&d_sumall[f * D_HID + j], sa);
    atomicAdd(&d_sumpos[f * D_HID + j], sp);
    atomicAdd(&d_sumneg[f * D_HID + j], sn);
}

__global__ void statsfinal_kernel() {
    int j = threadIdx.x;           // 0..1023
    int cp = 0, cn = 0;
    for (int f = 0; f < NF; f++) { cp += d_cntp[f]; cn += d_cntn[f]; }
    float sp = 0.0f, sn = 0.0f;
    for (int f = 0; f < NF; f++) { sp += d_sumpos[f * D_HID + j]; sn += d_sumneg[f * D_HID + j]; }
    float mp = sp / (float)max(cp, 1);
    float mn = sn / (float)max(cn, 1);
    d_meanp[j] = mp; d_meann[j] = mn;
    float g = 0.0f;
    for (int f = 0; f < NF; f++) {
        float adj = d_sumall[f * D_HID + j];
        if (cp >= 2) adj += 0.1f * ((float)d_cntp[f] * mp - d_sumpos[f * D_HID + j]);
        if (cn >= 2) adj += 0.1f * ((float)d_cntn[f] * mn - d_sumneg[f * D_HID + j]);
        float F = adj * (1.0f / (float)FS);
        d_F[f * D_HID + j] = F;
        g += F;
    }
    d_gop[j] = g * (1.0f / (float)NF);
    if (j == 0) { d_cnt_tot[0] = cp; d_cnt_tot[1] = cn; }
}

// apply syncs + debate; 4 elems per thread from fp16 hpost, scalar fp32 stores
// (out + 513 is only 4-byte aligned -> no vector stores)
__global__ void final_kernel(const int* __restrict__ pos, const int* __restrict__ step,
                             float* __restrict__ out) {
    size_t t = (size_t)blockIdx.x * 256 + threadIdx.x;   // 0 .. 4.19M
    int i = (int)(t >> 8);
    int j = (int)(t & 255) * 4;
    const __half2* hp = reinterpret_cast<const __half2*>(d_hpost_h + (size_t)i * 1024 + j);
    float2 a0 = __half22float2(hp[0]);
    float2 a1 = __half22float2(hp[1]);
    float hv[4] = {a0.x, a0.y, a1.x, a1.y};
    int p = pos[i];
    int cp = d_cnt_tot[0], cn = d_cnt_tot[1];
    if (p > 0 && cp >= 2) {
        const float4 m4 = *reinterpret_cast<const float4*>(d_meanp + j);
        const float* mv = (const float*)&m4;
#pragma unroll
        for (int q = 0; q < 4; q++) hv[q] = 0.9f * hv[q] + 0.1f * mv[q];
    } else if (p < 0 && cn >= 2) {
        const float4 m4 = *reinterpret_cast<const float4*>(d_meann + j);
        const float* mv = (const float*)&m4;
#pragma unroll
        for (int q = 0; q < 4; q++) hv[q] = 0.9f * hv[q] + 0.1f * mv[q];
    }
    int f = i >> 11;
    const float4 F4 = *reinterpret_cast<const float4*>(d_F + f * D_HID + j);
    const float* Fv = (const float*)&F4;
#pragma unroll
    for (int q = 0; q < 4; q++) hv[q] = 0.85f * hv[q] + 0.15f * Fv[q];
    if (*step > 5 && (i & (FS - 1)) < (FS / 4)) {
        const float4 g4 = *reinterpret_cast<const float4*>(d_gop + j);
        const float* gv = (const float*)&g4;
#pragma unroll
        for (int q = 0; q < 4; q++) hv[q] = 0.85f * hv[q] + 0.15f * gv[q];
    }
    float* o = out + 513 + (size_t)i * 1024 + j;
#pragma unroll
    for (int q = 0; q < 4; q++) o[q] = hv[q];
}

// combined_out = sum_i softmax(tension)_i * output[i,:]; 256 blocks x 64 rows
__global__ void wsum_kernel() {
    int r0 = blockIdx.x * 64;
    float inv = 1.0f / d_sumexp;
    int t = threadIdx.x;
    float c0 = 0.0f, c1 = 0.0f;
    for (int r = r0; r < r0 + 64; r++) {
        float w = d_ebuf[r] * inv;
        const __half* o = d_soutput_h + (size_t)r * 512;
        c0 += w * __half2float(o[t]);
        c1 += w * __half2float(o[t + 256]);
    }
    atomicAdd(&d_cout[t], c0);
    atomicAdd(&d_cout[t + 256], c1);
}

// split-K GEMV: out[t] += sum_{k in chunk} cout[k]*Wo[k][t]; bias seeded in prep
__global__ void pred_kernel(const float* __restrict__ Wo, float* __restrict__ out) {
    __shared__ float co[64];
    int b = blockIdx.x;      // 0..7
    int t = threadIdx.x;     // 0..511
    if (t < 64) co[t] = d_cout[b * 64 + t];
    __syncthreads();
    float s = 0.0f;
#pragma unroll 8
    for (int k = 0; k < 64; k++) s += co[k] * Wo[(size_t)(b * 64 + k) * 512 + t];
    atomicAdd(&out[t], s);
    if (b == 0 && t == 0) out[512] = d_tsum * (1.0f / (float)N_CELLS);
}

// ---------------- launch ----------------
extern "C" void kernel_launch(void* const* d_in, const int* in_sizes, int n_in,
                              void* d_out, int out_size) {
    const float* x        = (const float*)d_in[0];
    const float* hiddens  = (const float*)d_in[1];
    const float* wealth   = (const float*)d_in[2];
    const float* Wa1      = (const float*)d_in[3];
    const float* ba1      = (const float*)d_in[4];
    const float* Wa2      = (const float*)d_in[5];
    const float* ba2      = (const float*)d_in[6];
    const float* Wg1      = (const float*)d_in[7];
    const float* bg1      = (const float*)d_in[8];
    const float* Wg2      = (const float*)d_in[9];
    const float* bg2      = (const float*)d_in[10];
    const float* W_ih     = (const float*)d_in[11];
    const float* W_hh     = (const float*)d_in[12];
    const float* b_ih     = (const float*)d_in[13];
    const float* b_hh     = (const float*)d_in[14];
    const float* Wo       = (const float*)d_in[15];
    const float* bo       = (const float*)d_in[16];
    const int*   positions= (const int*)d_in[17];
    const int*   step     = (const int*)d_in[18];
    float* out = (float*)d_out;

    void *p_srelu_h, *p_w2h, *p_wbig, *p_biasbig, *p_wgi, *p_bcat;
    void *p_hid_h, *p_wih_t;
    cudaGetSymbolAddress(&p_srelu_h,   d_srelu_h);
    cudaGetSymbolAddress(&p_w2h,       d_w2h);
    cudaGetSymbolAddress(&p_wbig,      d_wbig);
    cudaGetSymbolAddress(&p_biasbig,   d_biasbig);
    cudaGetSymbolAddress(&p_wgi,       d_wgi);
    cudaGetSymbolAddress(&p_bcat,      d_bcat);
    cudaGetSymbolAddress(&p_hid_h,     d_hid_h);
    cudaGetSymbolAddress(&p_wih_t,     d_wih_t);

    const int SMEM_BYTES = 3 * STAGE_H * 2;   // 61440
    cudaFuncSetAttribute(gemm_fp16,
                         cudaFuncAttributeMaxDynamicSharedMemorySize, SMEM_BYTES);

    prep_all<<<22696, 256>>>(hiddens, W_hh, W_ih, x,
                             Wa1, ba1, Wg1, bg1, Wa2, ba2, Wg2, bg2,
                             b_hh, bo, positions, out);                      // 1

    // fused: [gh | H1] = hid @ [W_hh | W1] + [b_hh | xvec]  [112 GF]
    gemm_fp16<<<dim3(26, 128), 256, SMEM_BYTES>>>(                           // 2
        (const __half*)p_hid_h, 1024, (const __half*)p_wbig,
        nullptr, nullptr, 0, 1024, 4, (const float*)p_biasbig);

    // W2W^T [3072 x 256] = wih_t @ w2h^T -> wgi rows 512..3583
    gemm_fp16<<<dim3(2, 24), 256, SMEM_BYTES>>>(                             // 3
        (const __half*)p_wih_t, 512, (const __half*)p_w2h,
        nullptr, (__half*)p_wgi + (size_t)512 * 256, 256, 512, 8 | 16 | 32,
        nullptr);

    beff_kernel<<<384, 256>>>(b_ih);                                         // 4

    // fused: [soutput | gi] = H1 @ [W2cat | W2W] + [bias2 | beff]  [30 GF, K=256]
    gemm_fp16<<<dim3(28, 128), 256, SMEM_BYTES>>>(                           // 5
        (const __half*)p_srelu_h, 256, (const __half*)p_wgi,
        nullptr, nullptr, 0, 256, 64, (const float*)p_bcat);

    tension_kernel<<<2048, 256>>>();                                         // 6
    gru_kernel<<<32768, 256>>>(wealth, W_ih + (size_t)512 * 3072);           // 7
    stats_kernel<<<dim3(8, 8, 8), 128>>>(positions);                         // 8
    statsfinal_kernel<<<1, 1024>>>();                                        // 9
    final_kernel<<<16384, 256>>>(positions, step, out);                      // 10
    wsum_kernel<<<256, 256>>>();                                             // 11
    pred_kernel<<<8, 512>>>(Wo, out);                                        // 12
}